// round 8
// baseline (speedup 1.0000x reference)
#include <cuda_runtime.h>
#include <math.h>

// Problem dims
#define CB   64      // batch
#define CL   40      // seq len
#define CT   39      // decoder steps (L-1)
#define CH   512     // hidden
#define CDF  2048    // feature dim
#define CE   512     // embedding dim
#define CV   20000   // vocab
#define G4   2048    // 4*H

typedef unsigned long long u64;

// ---------------- scratch ----------------
constexpr int OFF_X    = 0;
constexpr int OFF_GINF = OFF_X    + CB*CL*CH;
constexpr int OFF_GINB = OFF_GINF + CB*CL*G4;
constexpr int OFF_HF   = OFF_GINB + CB*CL*G4;
constexpr int OFF_HB   = OFF_HF   + CL*CB*CH;
constexpr int OFF_HD   = OFF_HB   + CL*CB*CH;     // hD layout [B][T][H]
constexpr int OFF_CF   = OFF_HD   + CB*CT*CH;
constexpr int OFF_CB2  = OFF_CF   + CB*CH;
constexpr int OFF_CD   = OFF_CB2  + CB*CH;
constexpr int OFF_HZ   = OFF_CD   + CB*CH;
constexpr int OFF_CTX  = OFF_HZ   + CB*CH;
constexpr int OFF_DEMB = OFF_CTX  + CB*2*CH;
constexpr int OFF_EMBW = OFF_DEMB + CT*CB*CE;
constexpr int OFF_CTXW = OFF_EMBW + CT*CB*G4;
constexpr int OFF_PART = OFF_CTXW + CB*G4;
constexpr int SCRATCH_TOTAL = OFF_PART + 4*CB*G4;

__device__ float g_scratch[SCRATCH_TOTAL];
__device__ unsigned g_bar = 0;   // grid barrier counter (always 0 between launches)

// ---------------- helpers ----------------
__device__ __forceinline__ void fma2(u64 &d, u64 a, u64 b) {
    asm("fma.rn.f32x2 %0, %1, %2, %0;" : "+l"(d) : "l"(a), "l"(b));
}
__device__ __forceinline__ float pairsum(u64 v) {
    float lo = __uint_as_float((unsigned)(v & 0xffffffffull));
    float hi = __uint_as_float((unsigned)(v >> 32));
    return lo + hi;
}
__device__ __forceinline__ void sts4(float* dst, float4 v) {
    *reinterpret_cast<float2*>(dst)     = make_float2(v.x, v.y);
    *reinterpret_cast<float2*>(dst + 2) = make_float2(v.z, v.w);
}

// ---------------- grid barrier (all blocks resident; grid = 128) ----------------
__device__ __forceinline__ void grid_bar(unsigned &target) {
    __syncthreads();
    target += 128u;
    if (threadIdx.x == 0) {
        __threadfence();                       // release (emits CCTL.IVALL: L1 coherency)
        atomicAdd(&g_bar, 1u);
        unsigned v;
        do {
            asm volatile("ld.volatile.global.u32 %0, [%1];" : "=r"(v) : "l"(&g_bar));
        } while (v < target);
        __threadfence();                       // acquire
    }
    __syncthreads();
}
__device__ __forceinline__ void grid_bar_final(unsigned target) {
    __syncthreads();
    if (threadIdx.x == 0) {
        __threadfence();
        unsigned old = atomicAdd(&g_bar, 1u);
        if (old == target + 127u) {            // last arriver resets for next launch
            __threadfence();
            asm volatile("st.volatile.global.u32 [%0], %1;" :: "l"(&g_bar), "r"(0u));
        }
    }
}

// ================= big GEMM v2: C[M,N] = A[M,K]*W[N,K]^T (+b0+b1) =================
// BM=128, BN=128, BK=16; 256 thr; thread tile 8m x 8n; f32x2 packed along N.
// A duplicated in smem so LDS.128 yields two (a,a) pairs; W stored k-major.
__global__ __launch_bounds__(256, 2) void gemm_big2(
    const float* __restrict__ A, int lda,
    const float* __restrict__ W, int ldw,
    float* __restrict__ C, int ldc,
    int M, int N, int K,
    const float* __restrict__ bias0, const float* __restrict__ bias1)
{
    __shared__ float As2[16 * 256];   // [k][2*m]  (each a stored twice)
    __shared__ float Wsm[16 * 128];   // [k][n]
    const int tid  = threadIdx.x;
    const int m0   = blockIdx.x * 128;
    const int n0   = blockIdx.y * 128;
    const int warp = tid >> 5, lane = tid & 31;
    const int tm   = (warp & 3) * 32 + (lane >> 3) * 8;   // 8 m rows: tm..tm+7
    const int tn   = (warp >> 2) * 64 + (lane & 7) * 8;   // 8 n cols: tn..tn+7
    const int srow = tid >> 2;          // 0..63 staging row
    const int sq   = (tid & 3) * 4;     // staging k quad

    u64 acc[8][4];
#pragma unroll
    for (int i = 0; i < 8; i++)
#pragma unroll
        for (int j = 0; j < 4; j++) acc[i][j] = 0ull;

    const int nk = K >> 4;
    const float4 z4 = make_float4(0.f, 0.f, 0.f, 0.f);
    float4 pa[2], pw[2];
#pragma unroll
    for (int r = 0; r < 2; r++) {
        int ma = m0 + srow + 64 * r;
        pa[r] = (ma < M) ? *reinterpret_cast<const float4*>(A + (long)ma * lda + sq) : z4;
        int nw = n0 + srow + 64 * r;
        pw[r] = (nw < N) ? *reinterpret_cast<const float4*>(W + (long)nw * ldw + sq) : z4;
    }

    for (int c = 0; c < nk; c++) {
#pragma unroll
        for (int r = 0; r < 2; r++) {
            int m2 = 2 * (srow + 64 * r);
            As2[(sq + 0) * 256 + m2] = pa[r].x; As2[(sq + 0) * 256 + m2 + 1] = pa[r].x;
            As2[(sq + 1) * 256 + m2] = pa[r].y; As2[(sq + 1) * 256 + m2 + 1] = pa[r].y;
            As2[(sq + 2) * 256 + m2] = pa[r].z; As2[(sq + 2) * 256 + m2 + 1] = pa[r].z;
            As2[(sq + 3) * 256 + m2] = pa[r].w; As2[(sq + 3) * 256 + m2 + 1] = pa[r].w;
            int n = srow + 64 * r;
            Wsm[(sq + 0) * 128 + n] = pw[r].x;
            Wsm[(sq + 1) * 128 + n] = pw[r].y;
            Wsm[(sq + 2) * 128 + n] = pw[r].z;
            Wsm[(sq + 3) * 128 + n] = pw[r].w;
        }
        __syncthreads();

        if (c + 1 < nk) {
            int kc = (c + 1) << 4;
#pragma unroll
            for (int r = 0; r < 2; r++) {
                int ma = m0 + srow + 64 * r;
                pa[r] = (ma < M) ? *reinterpret_cast<const float4*>(A + (long)ma * lda + kc + sq) : z4;
                int nw = n0 + srow + 64 * r;
                pw[r] = (nw < N) ? *reinterpret_cast<const float4*>(W + (long)nw * ldw + kc + sq) : z4;
            }
        }

#pragma unroll
        for (int k = 0; k < 16; k++) {
            const float* ak = As2 + k * 256 + 2 * tm;   // 16B-aligned
            const float* wk = Wsm + k * 128 + tn;       // 16B-aligned? (tn mult of 8 -> 32B) yes
            ulonglong2 aA = *reinterpret_cast<const ulonglong2*>(ak);
            ulonglong2 aB = *reinterpret_cast<const ulonglong2*>(ak + 4);
            ulonglong2 aC = *reinterpret_cast<const ulonglong2*>(ak + 8);
            ulonglong2 aD = *reinterpret_cast<const ulonglong2*>(ak + 12);
            ulonglong2 wA = *reinterpret_cast<const ulonglong2*>(wk);
            ulonglong2 wB = *reinterpret_cast<const ulonglong2*>(wk + 4);
            u64 a2[8] = {aA.x, aA.y, aB.x, aB.y, aC.x, aC.y, aD.x, aD.y};
            u64 w2[4] = {wA.x, wA.y, wB.x, wB.y};
#pragma unroll
            for (int i = 0; i < 8; i++)
#pragma unroll
                for (int j = 0; j < 4; j++) fma2(acc[i][j], a2[i], w2[j]);
        }
        __syncthreads();
    }

#pragma unroll
    for (int i = 0; i < 8; i++) {
        int m = m0 + tm + i;
        if (m >= M) continue;
#pragma unroll
        for (int j = 0; j < 4; j++) {
            int n = n0 + tn + 2 * j;
            if (n >= N) continue;   // N even & n even => n+1 < N too
            float lo = __uint_as_float((unsigned)(acc[i][j] & 0xffffffffull));
            float hi = __uint_as_float((unsigned)(acc[i][j] >> 32));
            if (bias0) { lo += bias0[n]; hi += bias0[n + 1]; }
            if (bias1) { lo += bias1[n]; hi += bias1[n + 1]; }
            *reinterpret_cast<float2*>(C + (long)m * ldc + n) = make_float2(lo, hi);
        }
    }
}

// ---------------- small-M GEMM (standalone, used once for ctx @ Wih_d[:,E:]) ----------------
__global__ __launch_bounds__(256) void gemm_small64(
    const float* __restrict__ A, int lda,
    const float* __restrict__ W, int ldw,
    float* __restrict__ P, int N, int Kps)
{
    __shared__ float As[64][34];
    __shared__ float Ws[32][34];
    const int tid  = threadIdx.x;
    const int n0   = blockIdx.x * 32;
    const int kb   = blockIdx.y * Kps;
    const int tm   = tid >> 4;
    const int tn   = tid & 15;
    const int lrow = tid >> 3;
    const int lcol = (tid & 7) << 2;

    u64 acc[4][2];
#pragma unroll
    for (int i = 0; i < 4; i++) { acc[i][0] = 0ull; acc[i][1] = 0ull; }

    const int nk = Kps >> 5;
    float4 pa0, pa1, pw;
    {
        int k = kb + lcol;
        pa0 = *reinterpret_cast<const float4*>(A + (long)lrow * lda + k);
        pa1 = *reinterpret_cast<const float4*>(A + (long)(lrow + 32) * lda + k);
        pw  = *reinterpret_cast<const float4*>(W + (long)(n0 + lrow) * ldw + k);
    }
    for (int c = 0; c < nk; c++) {
        sts4(&As[lrow][lcol],      pa0);
        sts4(&As[lrow + 32][lcol], pa1);
        sts4(&Ws[lrow][lcol],      pw);
        __syncthreads();
        if (c + 1 < nk) {
            int k = kb + ((c + 1) << 5) + lcol;
            pa0 = *reinterpret_cast<const float4*>(A + (long)lrow * lda + k);
            pa1 = *reinterpret_cast<const float4*>(A + (long)(lrow + 32) * lda + k);
            pw  = *reinterpret_cast<const float4*>(W + (long)(n0 + lrow) * ldw + k);
        }
#pragma unroll
        for (int kk = 0; kk < 16; kk++) {
            u64 a2[4], w2[2];
#pragma unroll
            for (int i = 0; i < 4; i++)
                a2[i] = *reinterpret_cast<const u64*>(&As[tm + 16 * i][kk << 1]);
#pragma unroll
            for (int j = 0; j < 2; j++)
                w2[j] = *reinterpret_cast<const u64*>(&Ws[tn + 16 * j][kk << 1]);
#pragma unroll
            for (int i = 0; i < 4; i++)
#pragma unroll
                for (int j = 0; j < 2; j++) fma2(acc[i][j], a2[i], w2[j]);
        }
        __syncthreads();
    }
    float* out = P + (long)blockIdx.y * 64 * N;
#pragma unroll
    for (int i = 0; i < 4; i++)
#pragma unroll
        for (int j = 0; j < 2; j++)
            out[(tm + 16 * i) * (long)N + n0 + tn + 16 * j] = pairsum(acc[i][j]);
}

// ---------------- persistent LSTM: step GEMM + gates fused with grid barriers ----------------
// step GEMM: part[kz][64][2048] += h[64,512(lda)] x Whh[2048,512]^T, 128 blocks (64 n x 2 k)
__device__ __forceinline__ void step_gemm(const float* __restrict__ A, int lda,
                                          const float* __restrict__ W,
                                          float* __restrict__ part, int bx)
{
    __shared__ float As[64][34];
    __shared__ float Ws[32][34];
    const int tid  = threadIdx.x;
    const int n0   = (bx & 63) * 32;
    const int kb   = (bx >> 6) * 256;
    const int tm   = tid >> 4;
    const int tn   = tid & 15;
    const int lrow = tid >> 3;
    const int lcol = (tid & 7) << 2;

    u64 acc[4][2];
#pragma unroll
    for (int i = 0; i < 4; i++) { acc[i][0] = 0ull; acc[i][1] = 0ull; }

    float4 pa0, pa1, pw;
    {
        int k = kb + lcol;
        pa0 = *reinterpret_cast<const float4*>(A + (long)lrow * lda + k);
        pa1 = *reinterpret_cast<const float4*>(A + (long)(lrow + 32) * lda + k);
        pw  = *reinterpret_cast<const float4*>(W + (long)(n0 + lrow) * CH + k);
    }
    for (int c = 0; c < 8; c++) {                   // 8 chunks x 32k = 256k
        sts4(&As[lrow][lcol],      pa0);
        sts4(&As[lrow + 32][lcol], pa1);
        sts4(&Ws[lrow][lcol],      pw);
        __syncthreads();
        if (c < 7) {
            int k = kb + ((c + 1) << 5) + lcol;
            pa0 = *reinterpret_cast<const float4*>(A + (long)lrow * lda + k);
            pa1 = *reinterpret_cast<const float4*>(A + (long)(lrow + 32) * lda + k);
            pw  = *reinterpret_cast<const float4*>(W + (long)(n0 + lrow) * CH + k);
        }
#pragma unroll
        for (int kk = 0; kk < 16; kk++) {
            u64 a2[4], w2[2];
#pragma unroll
            for (int i = 0; i < 4; i++)
                a2[i] = *reinterpret_cast<const u64*>(&As[tm + 16 * i][kk << 1]);
#pragma unroll
            for (int j = 0; j < 2; j++)
                w2[j] = *reinterpret_cast<const u64*>(&Ws[tn + 16 * j][kk << 1]);
#pragma unroll
            for (int i = 0; i < 4; i++)
#pragma unroll
                for (int j = 0; j < 2; j++) fma2(acc[i][j], a2[i], w2[j]);
        }
        __syncthreads();
    }
    float* out = part + (long)(bx >> 6) * 64 * G4;
#pragma unroll
    for (int i = 0; i < 4; i++)
#pragma unroll
        for (int j = 0; j < 2; j++)
            out[(tm + 16 * i) * G4 + n0 + tn + 16 * j] = pairsum(acc[i][j]);
}

__device__ __forceinline__ void gates_fn(const float* P, const float* D1, int ldd1,
                                         const float* D2, float* c,
                                         float* h_out, int h_ld, int idx)
{
    int b = idx >> 9, u = idx & 511;
    const float* g0 = P + (long)b * G4;
    const float* g1 = P + (long)CB * G4 + (long)b * G4;
    const float* d1 = D1 + (long)b * ldd1;
    float gi = g0[u]        + g1[u]        + d1[u];
    float gf = g0[512 + u]  + g1[512 + u]  + d1[512 + u];
    float gg = g0[1024 + u] + g1[1024 + u] + d1[1024 + u];
    float go = g0[1536 + u] + g1[1536 + u] + d1[1536 + u];
    if (D2) {
        const float* d2 = D2 + (long)b * G4;
        gi += d2[u]; gf += d2[512 + u]; gg += d2[1024 + u]; go += d2[1536 + u];
    }
    float i_ = 1.f / (1.f + expf(-gi));
    float f_ = 1.f / (1.f + expf(-gf));
    float g_ = tanhf(gg);
    float o_ = 1.f / (1.f + expf(-go));
    float cn = f_ * c[idx] + i_ * g_;
    c[idx] = cn;
    h_out[(long)b * h_ld + u] = o_ * tanhf(cn);
}

__global__ __launch_bounds__(256) void lstm_persist(
    const float* __restrict__ Whh,
    const float* __restrict__ gin, long gin_step, int gin_ld,
    const float* __restrict__ D2,
    const float* __restrict__ hz,
    float* __restrict__ hbase, long h_step, int h_ld,
    float* __restrict__ c, float* __restrict__ part,
    int nsteps, int dir)
{
    unsigned target = 0;
    const int bx = blockIdx.x;
    const int idx = bx * 256 + threadIdx.x;
    for (int s = 0; s < nsteps; s++) {
        int l = (dir > 0) ? s : (nsteps - 1 - s);
        const float* hin; int hlda;
        if (s == 0) { hin = hz; hlda = CH; }
        else {
            int lp = (dir > 0) ? (l - 1) : (l + 1);
            hin = hbase + (long)lp * h_step; hlda = h_ld;
        }
        step_gemm(hin, hlda, Whh, part, bx);
        grid_bar(target);                      // part ready -> gates
        gates_fn(part, gin + (long)l * gin_step, gin_ld, D2, c,
                 hbase + (long)l * h_step, h_ld, idx);
        if (s + 1 < nsteps) grid_bar(target);  // h ready -> next step GEMM
        else                grid_bar_final(target);
    }
}

// ---------------- small elementwise kernels ----------------
__global__ void zero_state(float* cF, float* cB, float* cD, float* hz)
{
    int idx = blockIdx.x * blockDim.x + threadIdx.x;
    cF[idx] = 0.f; cB[idx] = 0.f; cD[idx] = 0.f; hz[idx] = 0.f;
}

__global__ void ctx_sum(const float* __restrict__ hF, const float* __restrict__ hB,
                        float* __restrict__ ctx)
{
    int idx = blockIdx.x * blockDim.x + threadIdx.x;  // 64*1024
    int b = idx >> 10, j = idx & 1023;
    float s = 0.f;
    if (j < 512) {
        for (int l = 0; l < CL; l++) s += hF[((long)l * CB + b) * CH + j];
    } else {
        int j2 = j - 512;
        for (int l = 0; l < CL; l++) s += hB[((long)l * CB + b) * CH + j2];
    }
    ctx[idx] = s;
}

__global__ void ctx_combine(const float* __restrict__ P,
                            const float* __restrict__ b0,
                            const float* __restrict__ b1,
                            float* __restrict__ ctxW)
{
    int idx = blockIdx.x * blockDim.x + threadIdx.x;  // 64*2048
    int b = idx >> 11, n = idx & 2047;
    float s = b0[n] + b1[n];
#pragma unroll
    for (int z = 0; z < 4; z++) s += P[((long)z * CB + b) * G4 + n];
    ctxW[idx] = s;
}

__global__ void gather_emb(const float* __restrict__ emb, const int* __restrict__ targets,
                           float* __restrict__ dst)
{
    int idx = blockIdx.x * blockDim.x + threadIdx.x;  // 39*64*512
    int e = idx & 511;
    int r = idx >> 9;
    int t = r / CB, b = r - t * CB;
    int tgt = targets[b * CL + t];
    dst[idx] = emb[(long)tgt * CE + e];
}

// ---------------- launch ----------------
extern "C" void kernel_launch(void* const* d_in, const int* in_sizes, int n_in,
                              void* d_out, int out_size)
{
    (void)in_sizes; (void)n_in; (void)out_size;
    const float* feats  = (const float*)d_in[0];
    const float* feat_W = (const float*)d_in[1];
    const float* feat_b = (const float*)d_in[2];
    const float* Wih_f  = (const float*)d_in[3];
    const float* Whh_f  = (const float*)d_in[4];
    const float* bih_f  = (const float*)d_in[5];
    const float* bhh_f  = (const float*)d_in[6];
    const float* Wih_b  = (const float*)d_in[7];
    const float* Whh_b  = (const float*)d_in[8];
    const float* bih_b  = (const float*)d_in[9];
    const float* bhh_b  = (const float*)d_in[10];
    const float* emb    = (const float*)d_in[11];
    const float* Wih_d  = (const float*)d_in[12];
    const float* Whh_d  = (const float*)d_in[13];
    const float* bih_d  = (const float*)d_in[14];
    const float* bhh_d  = (const float*)d_in[15];
    // d_in[16..20]: attention params — provably unused (softmax over singleton axis -> ones)
    const float* out_W  = (const float*)d_in[21];
    const float* out_b  = (const float*)d_in[22];
    const int*   targets = (const int*)d_in[23];
    float* out = (float*)d_out;

    float* S = nullptr;
    cudaGetSymbolAddress((void**)&S, g_scratch);
    float* x     = S + OFF_X;
    float* ginF  = S + OFF_GINF;
    float* ginB  = S + OFF_GINB;
    float* hF    = S + OFF_HF;
    float* hB    = S + OFF_HB;
    float* hD    = S + OFF_HD;
    float* cF    = S + OFF_CF;
    float* cBb   = S + OFF_CB2;
    float* cD    = S + OFF_CD;
    float* hz    = S + OFF_HZ;
    float* ctx   = S + OFF_CTX;
    float* demb  = S + OFF_DEMB;
    float* embW  = S + OFF_EMBW;
    float* ctxW  = S + OFF_CTXW;
    float* part  = S + OFF_PART;

    zero_state<<<128, 256>>>(cF, cBb, cD, hz);

    // x = feats @ feat_W^T + feat_b      [2560,2048] x [512,2048]^T
    gemm_big2<<<dim3(20, 4), 256>>>(feats, CDF, feat_W, CDF, x, CH, CB * CL, CH, CDF,
                                    feat_b, nullptr);
    // encoder input-gate precompute (biases folded)
    gemm_big2<<<dim3(20, 16), 256>>>(x, CH, Wih_f, CH, ginF, G4, CB * CL, G4, CH, bih_f, bhh_f);
    gemm_big2<<<dim3(20, 16), 256>>>(x, CH, Wih_b, CH, ginB, G4, CB * CL, G4, CH, bih_b, bhh_b);

    // forward + backward LSTMs as single persistent kernels
    lstm_persist<<<128, 256>>>(Whh_f, ginF, (long)G4, CL * G4, nullptr, hz,
                               hF, (long)CB * CH, CH, cF, part, CL, +1);
    lstm_persist<<<128, 256>>>(Whh_b, ginB, (long)G4, CL * G4, nullptr, hz,
                               hB, (long)CB * CH, CH, cBb, part, CL, -1);

    // ctx[b] = sum_l enc[b,l,:]
    ctx_sum<<<256, 256>>>(hF, hB, ctx);

    // decoder input-gate precompute
    gather_emb<<<(CT * CB * CE) / 256, 256>>>(emb, targets, demb);
    gemm_big2<<<dim3(20, 16), 256>>>(demb, CE, Wih_d, 2 * CH + CE, embW, G4, CT * CB, G4, CE,
                                     nullptr, nullptr);
    gemm_small64<<<dim3(64, 4), 256>>>(ctx, 2 * CH, Wih_d + CE, 2 * CH + CE, part, G4, 256);
    ctx_combine<<<512, 256>>>(part, bih_d, bhh_d, ctxW);

    // decoder LSTM persistent (hD layout [B][T][H])
    lstm_persist<<<128, 256>>>(Whh_d, embW, (long)CB * G4, G4, ctxW, hz,
                               hD, (long)CH, CT * CH, cD, part, CT, +1);

    // output projection: out[b,t,:] = hD[b,t,:] @ out_W^T + out_b
    gemm_big2<<<dim3(20, 157), 256>>>(hD, CH, out_W, CH, out, CV, CT * CB, CV, CH,
                                      out_b, nullptr);
}

// round 10
// speedup vs baseline: 1.7903x; 1.7903x over previous
#include <cuda_runtime.h>
#include <cuda_bf16.h>
#include <math.h>
#include <stdint.h>

// Problem dims
#define CB   64      // batch
#define CL   40      // seq len
#define CT   39      // decoder steps (L-1)
#define CH   512     // hidden
#define CDF  2048    // feature dim
#define CE   512     // embedding dim
#define CV   20000   // vocab
#define G4   2048    // 4*H

typedef unsigned long long u64;

// ---------------- fp32 scratch ----------------
constexpr int OFF_X    = 0;
constexpr int OFF_GINF = OFF_X    + CB*CL*CH;
constexpr int OFF_GINB = OFF_GINF + CB*CL*G4;
constexpr int OFF_HF   = OFF_GINB + CB*CL*G4;
constexpr int OFF_HB   = OFF_HF   + CL*CB*CH;
constexpr int OFF_HD   = OFF_HB   + CL*CB*CH;     // hD layout [B][T][H] contiguous 2496x512
constexpr int OFF_CF   = OFF_HD   + CB*CT*CH;
constexpr int OFF_CB2  = OFF_CF   + CB*CH;
constexpr int OFF_CD   = OFF_CB2  + CB*CH;
constexpr int OFF_HZ   = OFF_CD   + CB*CH;
constexpr int OFF_CTX  = OFF_HZ   + CB*CH;
constexpr int OFF_DEMB = OFF_CTX  + CB*2*CH;
constexpr int OFF_EMBW = OFF_DEMB + CT*CB*CE;
constexpr int OFF_CTXW = OFF_EMBW + CT*CB*G4;
constexpr int OFF_PART = OFF_CTXW + CB*G4;
constexpr int SCRATCH_TOTAL = OFF_PART + 4*CB*G4;
__device__ __align__(256) float g_scratch[SCRATCH_TOTAL];
__device__ unsigned g_bar = 0;

// ---------------- bf16 hi/lo scratch (hi at off, lo at off + size) ----------------
constexpr long BO_WOUT  = 0;                               // 20096 x 512 (pad of 20000)
constexpr long BO_FW    = BO_WOUT  + 2L*20096*512;         // 512 x 2048
constexpr long BO_WIF   = BO_FW    + 2L*512*2048;          // 2048 x 512
constexpr long BO_WIB   = BO_WIF   + 2L*2048*512;
constexpr long BO_WID   = BO_WIB   + 2L*2048*512;          // 2048 x 512 (first E cols)
constexpr long BO_FEATS = BO_WID   + 2L*2048*512;          // 2560 x 2048
constexpr long BO_X     = BO_FEATS + 2L*2560*2048;         // 2560 x 512
constexpr long BO_DEMB  = BO_X     + 2L*2560*512;          // 2560 x 512 (pad of 2496)
constexpr long BO_HD    = BO_DEMB  + 2L*2560*512;          // 2560 x 512 (pad of 2496)
constexpr long BF_TOTAL = BO_HD    + 2L*2560*512;
__device__ __align__(256) __nv_bfloat16 g_bf[BF_TOTAL];

// ---------------- helpers ----------------
__device__ __forceinline__ void fma2(u64 &d, u64 a, u64 b) {
    asm("fma.rn.f32x2 %0, %1, %2, %0;" : "+l"(d) : "l"(a), "l"(b));
}
__device__ __forceinline__ float pairsum(u64 v) {
    float lo = __uint_as_float((unsigned)(v & 0xffffffffull));
    float hi = __uint_as_float((unsigned)(v >> 32));
    return lo + hi;
}
__device__ __forceinline__ void sts4(float* dst, float4 v) {
    *reinterpret_cast<float2*>(dst)     = make_float2(v.x, v.y);
    *reinterpret_cast<float2*>(dst + 2) = make_float2(v.z, v.w);
}
__device__ __forceinline__ uint32_t smem_u32(const void* p) {
    uint32_t a;
    asm("{ .reg .u64 t; cvta.to.shared.u64 t, %1; cvt.u32.u64 %0, t; }" : "=r"(a) : "l"(p));
    return a;
}
__device__ __forceinline__ void cp16(uint32_t dst, const void* src) {
    asm volatile("cp.async.cg.shared.global [%0], [%1], 16;" :: "r"(dst), "l"(src) : "memory");
}
__device__ __forceinline__ void cp_commit_wait0() {
    asm volatile("cp.async.commit_group;" ::: "memory");
    asm volatile("cp.async.wait_group 0;" ::: "memory");
}
__device__ __forceinline__ void ldsm4(uint32_t* r, uint32_t addr) {
    asm volatile("ldmatrix.sync.aligned.m8n8.x4.shared.b16 {%0,%1,%2,%3}, [%4];"
                 : "=r"(r[0]), "=r"(r[1]), "=r"(r[2]), "=r"(r[3]) : "r"(addr));
}
__device__ __forceinline__ void mma16816(float* d, const uint32_t* a, const uint32_t* b) {
    asm volatile("mma.sync.aligned.m16n8k16.row.col.f32.bf16.bf16.f32 "
                 "{%0,%1,%2,%3}, {%4,%5,%6,%7}, {%8,%9}, {%0,%1,%2,%3};"
                 : "+f"(d[0]), "+f"(d[1]), "+f"(d[2]), "+f"(d[3])
                 : "r"(a[0]), "r"(a[1]), "r"(a[2]), "r"(a[3]), "r"(b[0]), "r"(b[1]));
}
// swizzled element index for (row r, k-chunk c) in a [128][32] bf16 tile; 8 elems/chunk.
__device__ __forceinline__ int swzi(int r, int c) {
    int cc = (c + r + (r >> 2)) & 3;
    return r * 32 + cc * 8;
}

// ---------------- grid barrier (128 resident blocks) ----------------
__device__ __forceinline__ void grid_bar(unsigned &target) {
    __syncthreads();
    target += 128u;
    if (threadIdx.x == 0) {
        __threadfence();
        atomicAdd(&g_bar, 1u);
        unsigned v;
        do {
            asm volatile("ld.volatile.global.u32 %0, [%1];" : "=r"(v) : "l"(&g_bar));
        } while (v < target);
        __threadfence();
    }
    __syncthreads();
}
__device__ __forceinline__ void grid_bar_final(unsigned target) {
    __syncthreads();
    if (threadIdx.x == 0) {
        __threadfence();
        unsigned old = atomicAdd(&g_bar, 1u);
        if (old == target + 127u) {
            __threadfence();
            asm volatile("st.volatile.global.u32 [%0], %1;" :: "l"(&g_bar), "r"(0u));
        }
    }
}

// ================= split fp32 -> bf16 hi/lo (with row padding to zeros) ============
__global__ void split_bf16(const float* __restrict__ src, int ld, int rows_valid, int cols,
                           __nv_bfloat16* __restrict__ hi, long losz, long total)
{
    long idx = (long)blockIdx.x * 256 + threadIdx.x;
    if (idx >= total) return;
    long r = idx / cols;
    int  c = (int)(idx - r * cols);
    float v = (r < rows_valid) ? src[r * (long)ld + c] : 0.f;
    __nv_bfloat16 h = __float2bfloat16(v);
    float rem = v - __bfloat162float(h);
    hi[idx]        = h;
    hi[idx + losz] = __float2bfloat16(rem);
}

// ================= HMMA GEMM: C[M,N] = A[M,K] * W[N,K]^T (+b0+b1) ==============
// A,W as bf16 hi (lo at +size), row-major, rows padded to tile multiples.
// 128x128 tile, BK=32, 8 warps (2m x 4n), warp tile 64x32. bf16x3 split accuracy.
__global__ __launch_bounds__(256) void gemm_mma(
    const __nv_bfloat16* __restrict__ Ah, long Asz,
    const __nv_bfloat16* __restrict__ Wh, long Wsz,
    float* __restrict__ C, int ldc, int Mvalid, int N, int K,
    const float* __restrict__ bias0, const float* __restrict__ bias1)
{
    __shared__ __align__(128) __nv_bfloat16 sAh[128 * 32];
    __shared__ __align__(128) __nv_bfloat16 sAl[128 * 32];
    __shared__ __align__(128) __nv_bfloat16 sWh[128 * 32];
    __shared__ __align__(128) __nv_bfloat16 sWl[128 * 32];

    const int tid  = threadIdx.x;
    const int wid  = tid >> 5, lane = tid & 31;
    const int wm   = wid >> 2;          // 0..1  (64 rows each)
    const int wn   = wid & 3;           // 0..3  (32 cols each)
    const int m0   = blockIdx.x * 128, n0 = blockIdx.y * 128;

    const __nv_bfloat16* Al = Ah + Asz;
    const __nv_bfloat16* Wl = Wh + Wsz;

    const uint32_t bAh = smem_u32(sAh), bAl = smem_u32(sAl);
    const uint32_t bWh = smem_u32(sWh), bWl = smem_u32(sWl);

    float acc[4][4][4];
#pragma unroll
    for (int i = 0; i < 4; i++)
#pragma unroll
        for (int j = 0; j < 4; j++)
#pragma unroll
            for (int q = 0; q < 4; q++) acc[i][j][q] = 0.f;

    // per-lane ldmatrix address components
    const int a_r  = lane & 15;                       // row within 16
    const int a_cg = lane >> 4;                       // k-chunk half (0..1)
    const int b_r  = (lane & 7) + ((lane >> 4) << 3); // row within 16 (n)
    const int b_cg = (lane >> 3) & 1;                 // k-chunk half

    const int nch = K >> 5;
    for (int c = 0; c < nch; c++) {
        const int k0 = c << 5;
        // ---- fill 4 tiles via cp.async (swizzled) ----
#pragma unroll
        for (int g = 0; g < 2; g++) {
            int u  = tid + 256 * g;
            int r  = u >> 2, cc = u & 3;
            uint32_t so = (uint32_t)swzi(r, cc) * 2;
            long ga = (long)(m0 + r) * K + k0 + cc * 8;
            long gb = (long)(n0 + r) * K + k0 + cc * 8;
            cp16(bAh + so, Ah + ga);
            cp16(bAl + so, Al + ga);
            cp16(bWh + so, Wh + gb);
            cp16(bWl + so, Wl + gb);
        }
        cp_commit_wait0();
        __syncthreads();

        // ---- compute: two k16 steps ----
#pragma unroll
        for (int h = 0; h < 2; h++) {
            uint32_t ah[4][4], al[4][4];
#pragma unroll
            for (int t = 0; t < 4; t++) {
                int r  = wm * 64 + t * 16 + a_r;
                int ch = 2 * h + a_cg;
                uint32_t off = (uint32_t)swzi(r, ch) * 2;
                ldsm4(ah[t], bAh + off);
                ldsm4(al[t], bAl + off);
            }
            uint32_t bh[4][2], bl[4][2];
#pragma unroll
            for (int p = 0; p < 2; p++) {
                int r  = wn * 32 + p * 16 + b_r;
                int ch = 2 * h + b_cg;
                uint32_t off = (uint32_t)swzi(r, ch) * 2;
                uint32_t tmp[4];
                ldsm4(tmp, bWh + off);
                bh[2*p][0] = tmp[0]; bh[2*p][1] = tmp[1];
                bh[2*p+1][0] = tmp[2]; bh[2*p+1][1] = tmp[3];
                ldsm4(tmp, bWl + off);
                bl[2*p][0] = tmp[0]; bl[2*p][1] = tmp[1];
                bl[2*p+1][0] = tmp[2]; bl[2*p+1][1] = tmp[3];
            }
#pragma unroll
            for (int t = 0; t < 4; t++)
#pragma unroll
                for (int n = 0; n < 4; n++) {
                    mma16816(acc[t][n], ah[t], bh[n]);
                    mma16816(acc[t][n], ah[t], bl[n]);
                    mma16816(acc[t][n], al[t], bh[n]);
                }
        }
        __syncthreads();
    }

    // ---- epilogue ----
#pragma unroll
    for (int t = 0; t < 4; t++) {
#pragma unroll
        for (int n = 0; n < 4; n++) {
            int row = m0 + wm * 64 + t * 16 + (lane >> 2);
            int col = n0 + wn * 32 + n * 8 + 2 * (lane & 3);
            if (col < N) {
                float bx = 0.f, by = 0.f;
                if (bias0) { bx += bias0[col]; by += bias0[col + 1]; }
                if (bias1) { bx += bias1[col]; by += bias1[col + 1]; }
                if (row < Mvalid)
                    *reinterpret_cast<float2*>(C + (long)row * ldc + col) =
                        make_float2(acc[t][n][0] + bx, acc[t][n][1] + by);
                if (row + 8 < Mvalid)
                    *reinterpret_cast<float2*>(C + (long)(row + 8) * ldc + col) =
                        make_float2(acc[t][n][2] + bx, acc[t][n][3] + by);
            }
        }
    }
}

// ---------------- small-M GEMM (used once for ctx @ Wih_d[:,E:]) ----------------
__global__ __launch_bounds__(256) void gemm_small64(
    const float* __restrict__ A, int lda,
    const float* __restrict__ W, int ldw,
    float* __restrict__ P, int N, int Kps)
{
    __shared__ float As[64][34];
    __shared__ float Ws[32][34];
    const int tid  = threadIdx.x;
    const int n0   = blockIdx.x * 32;
    const int kb   = blockIdx.y * Kps;
    const int tm   = tid >> 4;
    const int tn   = tid & 15;
    const int lrow = tid >> 3;
    const int lcol = (tid & 7) << 2;

    u64 acc[4][2];
#pragma unroll
    for (int i = 0; i < 4; i++) { acc[i][0] = 0ull; acc[i][1] = 0ull; }

    const int nk = Kps >> 5;
    float4 pa0, pa1, pw;
    {
        int k = kb + lcol;
        pa0 = *reinterpret_cast<const float4*>(A + (long)lrow * lda + k);
        pa1 = *reinterpret_cast<const float4*>(A + (long)(lrow + 32) * lda + k);
        pw  = *reinterpret_cast<const float4*>(W + (long)(n0 + lrow) * ldw + k);
    }
    for (int c = 0; c < nk; c++) {
        sts4(&As[lrow][lcol],      pa0);
        sts4(&As[lrow + 32][lcol], pa1);
        sts4(&Ws[lrow][lcol],      pw);
        __syncthreads();
        if (c + 1 < nk) {
            int k = kb + ((c + 1) << 5) + lcol;
            pa0 = *reinterpret_cast<const float4*>(A + (long)lrow * lda + k);
            pa1 = *reinterpret_cast<const float4*>(A + (long)(lrow + 32) * lda + k);
            pw  = *reinterpret_cast<const float4*>(W + (long)(n0 + lrow) * ldw + k);
        }
#pragma unroll
        for (int kk = 0; kk < 16; kk++) {
            u64 a2[4], w2[2];
#pragma unroll
            for (int i = 0; i < 4; i++)
                a2[i] = *reinterpret_cast<const u64*>(&As[tm + 16 * i][kk << 1]);
#pragma unroll
            for (int j = 0; j < 2; j++)
                w2[j] = *reinterpret_cast<const u64*>(&Ws[tn + 16 * j][kk << 1]);
#pragma unroll
            for (int i = 0; i < 4; i++)
#pragma unroll
                for (int j = 0; j < 2; j++) fma2(acc[i][j], a2[i], w2[j]);
        }
        __syncthreads();
    }
    float* out = P + (long)blockIdx.y * 64 * N;
#pragma unroll
    for (int i = 0; i < 4; i++)
#pragma unroll
        for (int j = 0; j < 2; j++)
            out[(tm + 16 * i) * (long)N + n0 + tn + 16 * j] = pairsum(acc[i][j]);
}

// ---------------- persistent LSTM (step GEMM + fused gates, grid barriers) --------
__device__ __forceinline__ void step_gemm(const float* __restrict__ A, int lda,
                                          const float* __restrict__ W,
                                          float* __restrict__ part, int bx)
{
    __shared__ float As[64][34];
    __shared__ float Ws[32][34];
    const int tid  = threadIdx.x;
    const int n0   = (bx & 63) * 32;
    const int kb   = (bx >> 6) * 256;
    const int tm   = tid >> 4;
    const int tn   = tid & 15;
    const int lrow = tid >> 3;
    const int lcol = (tid & 7) << 2;

    u64 acc[4][2];
#pragma unroll
    for (int i = 0; i < 4; i++) { acc[i][0] = 0ull; acc[i][1] = 0ull; }

    float4 pa0, pa1, pw;
    {
        int k = kb + lcol;
        pa0 = *reinterpret_cast<const float4*>(A + (long)lrow * lda + k);
        pa1 = *reinterpret_cast<const float4*>(A + (long)(lrow + 32) * lda + k);
        pw  = *reinterpret_cast<const float4*>(W + (long)(n0 + lrow) * CH + k);
    }
    for (int c = 0; c < 8; c++) {
        sts4(&As[lrow][lcol],      pa0);
        sts4(&As[lrow + 32][lcol], pa1);
        sts4(&Ws[lrow][lcol],      pw);
        __syncthreads();
        if (c < 7) {
            int k = kb + ((c + 1) << 5) + lcol;
            pa0 = *reinterpret_cast<const float4*>(A + (long)lrow * lda + k);
            pa1 = *reinterpret_cast<const float4*>(A + (long)(lrow + 32) * lda + k);
            pw  = *reinterpret_cast<const float4*>(W + (long)(n0 + lrow) * CH + k);
        }
#pragma unroll
        for (int kk = 0; kk < 16; kk++) {
            u64 a2[4], w2[2];
#pragma unroll
            for (int i = 0; i < 4; i++)
                a2[i] = *reinterpret_cast<const u64*>(&As[tm + 16 * i][kk << 1]);
#pragma unroll
            for (int j = 0; j < 2; j++)
                w2[j] = *reinterpret_cast<const u64*>(&Ws[tn + 16 * j][kk << 1]);
#pragma unroll
            for (int i = 0; i < 4; i++)
#pragma unroll
                for (int j = 0; j < 2; j++) fma2(acc[i][j], a2[i], w2[j]);
        }
        __syncthreads();
    }
    float* out = part + (long)(bx >> 6) * 64 * G4;
#pragma unroll
    for (int i = 0; i < 4; i++)
#pragma unroll
        for (int j = 0; j < 2; j++)
            out[(tm + 16 * i) * G4 + n0 + tn + 16 * j] = pairsum(acc[i][j]);
}

__device__ __forceinline__ void gates_fn(const float* P, const float* D1, int ldd1,
                                         const float* D2, float* c,
                                         float* h_out, int h_ld, int idx)
{
    int b = idx >> 9, u = idx & 511;
    const float* g0 = P + (long)b * G4;
    const float* g1 = P + (long)CB * G4 + (long)b * G4;
    const float* d1 = D1 + (long)b * ldd1;
    float gi = g0[u]        + g1[u]        + d1[u];
    float gf = g0[512 + u]  + g1[512 + u]  + d1[512 + u];
    float gg = g0[1024 + u] + g1[1024 + u] + d1[1024 + u];
    float go = g0[1536 + u] + g1[1536 + u] + d1[1536 + u];
    if (D2) {
        const float* d2 = D2 + (long)b * G4;
        gi += d2[u]; gf += d2[512 + u]; gg += d2[1024 + u]; go += d2[1536 + u];
    }
    float i_ = 1.f / (1.f + expf(-gi));
    float f_ = 1.f / (1.f + expf(-gf));
    float g_ = tanhf(gg);
    float o_ = 1.f / (1.f + expf(-go));
    float cn = f_ * c[idx] + i_ * g_;
    c[idx] = cn;
    h_out[(long)b * h_ld + u] = o_ * tanhf(cn);
}

__global__ __launch_bounds__(256) void lstm_persist(
    const float* __restrict__ Whh,
    const float* __restrict__ gin, long gin_step, int gin_ld,
    const float* __restrict__ D2,
    const float* __restrict__ hz,
    float* __restrict__ hbase, long h_step, int h_ld,
    float* __restrict__ c, float* __restrict__ part,
    int nsteps, int dir)
{
    unsigned target = 0;
    const int bx = blockIdx.x;
    const int idx = bx * 256 + threadIdx.x;
    for (int s = 0; s < nsteps; s++) {
        int l = (dir > 0) ? s : (nsteps - 1 - s);
        const float* hin; int hlda;
        if (s == 0) { hin = hz; hlda = CH; }
        else {
            int lp = (dir > 0) ? (l - 1) : (l + 1);
            hin = hbase + (long)lp * h_step; hlda = h_ld;
        }
        step_gemm(hin, hlda, Whh, part, bx);
        grid_bar(target);
        gates_fn(part, gin + (long)l * gin_step, gin_ld, D2, c,
                 hbase + (long)l * h_step, h_ld, idx);
        if (s + 1 < nsteps) grid_bar(target);
        else                grid_bar_final(target);
    }
}

// ---------------- small elementwise kernels ----------------
__global__ void zero_state(float* cF, float* cB, float* cD, float* hz)
{
    int idx = blockIdx.x * blockDim.x + threadIdx.x;
    cF[idx] = 0.f; cB[idx] = 0.f; cD[idx] = 0.f; hz[idx] = 0.f;
}

__global__ void ctx_sum(const float* __restrict__ hF, const float* __restrict__ hB,
                        float* __restrict__ ctx)
{
    int idx = blockIdx.x * blockDim.x + threadIdx.x;  // 64*1024
    int b = idx >> 10, j = idx & 1023;
    float s = 0.f;
    if (j < 512) {
        for (int l = 0; l < CL; l++) s += hF[((long)l * CB + b) * CH + j];
    } else {
        int j2 = j - 512;
        for (int l = 0; l < CL; l++) s += hB[((long)l * CB + b) * CH + j2];
    }
    ctx[idx] = s;
}

__global__ void ctx_combine(const float* __restrict__ P,
                            const float* __restrict__ b0,
                            const float* __restrict__ b1,
                            float* __restrict__ ctxW)
{
    int idx = blockIdx.x * blockDim.x + threadIdx.x;  // 64*2048
    int b = idx >> 11, n = idx & 2047;
    float s = b0[n] + b1[n];
#pragma unroll
    for (int z = 0; z < 4; z++) s += P[((long)z * CB + b) * G4 + n];
    ctxW[idx] = s;
}

__global__ void gather_emb(const float* __restrict__ emb, const int* __restrict__ targets,
                           float* __restrict__ dst)
{
    int idx = blockIdx.x * blockDim.x + threadIdx.x;  // 39*64*512
    int e = idx & 511;
    int r = idx >> 9;
    int t = r / CB, b = r - t * CB;
    int tgt = targets[b * CL + t];
    dst[idx] = emb[(long)tgt * CE + e];
}

// ---------------- launch ----------------
static inline int sgrid(long n) { return (int)((n + 255) / 256); }

extern "C" void kernel_launch(void* const* d_in, const int* in_sizes, int n_in,
                              void* d_out, int out_size)
{
    (void)in_sizes; (void)n_in; (void)out_size;
    const float* feats  = (const float*)d_in[0];
    const float* feat_W = (const float*)d_in[1];
    const float* feat_b = (const float*)d_in[2];
    const float* Wih_f  = (const float*)d_in[3];
    const float* Whh_f  = (const float*)d_in[4];
    const float* bih_f  = (const float*)d_in[5];
    const float* bhh_f  = (const float*)d_in[6];
    const float* Wih_b  = (const float*)d_in[7];
    const float* Whh_b  = (const float*)d_in[8];
    const float* bih_b  = (const float*)d_in[9];
    const float* bhh_b  = (const float*)d_in[10];
    const float* emb    = (const float*)d_in[11];
    const float* Wih_d  = (const float*)d_in[12];
    const float* Whh_d  = (const float*)d_in[13];
    const float* bih_d  = (const float*)d_in[14];
    const float* bhh_d  = (const float*)d_in[15];
    // d_in[16..20]: attention params — provably unused (softmax over singleton axis -> ones)
    const float* out_W  = (const float*)d_in[21];
    const float* out_b  = (const float*)d_in[22];
    const int*   targets = (const int*)d_in[23];
    float* out = (float*)d_out;

    float* S = nullptr;
    cudaGetSymbolAddress((void**)&S, g_scratch);
    __nv_bfloat16* BF = nullptr;
    cudaGetSymbolAddress((void**)&BF, g_bf);

    float* x     = S + OFF_X;
    float* ginF  = S + OFF_GINF;
    float* ginB  = S + OFF_GINB;
    float* hF    = S + OFF_HF;
    float* hB    = S + OFF_HB;
    float* hD    = S + OFF_HD;
    float* cF    = S + OFF_CF;
    float* cBb   = S + OFF_CB2;
    float* cD    = S + OFF_CD;
    float* hz    = S + OFF_HZ;
    float* ctx   = S + OFF_CTX;
    float* demb  = S + OFF_DEMB;
    float* embW  = S + OFF_EMBW;
    float* ctxW  = S + OFF_CTXW;
    float* part  = S + OFF_PART;

    zero_state<<<128, 256>>>(cF, cBb, cD, hz);

    // ---- weight/input splits to bf16 hi/lo ----
    split_bf16<<<sgrid(20096L*512), 256>>>(out_W, 512, 20000, 512,
                                           BF + BO_WOUT, 20096L*512, 20096L*512);
    split_bf16<<<sgrid(512L*2048), 256>>>(feat_W, 2048, 512, 2048,
                                          BF + BO_FW, 512L*2048, 512L*2048);
    split_bf16<<<sgrid(2048L*512), 256>>>(Wih_f, 512, 2048, 512,
                                          BF + BO_WIF, 2048L*512, 2048L*512);
    split_bf16<<<sgrid(2048L*512), 256>>>(Wih_b, 512, 2048, 512,
                                          BF + BO_WIB, 2048L*512, 2048L*512);
    split_bf16<<<sgrid(2048L*512), 256>>>(Wih_d, 2*CH + CE, 2048, 512,
                                          BF + BO_WID, 2048L*512, 2048L*512);
    split_bf16<<<sgrid(2560L*2048), 256>>>(feats, 2048, 2560, 2048,
                                           BF + BO_FEATS, 2560L*2048, 2560L*2048);

    // x = feats @ feat_W^T + feat_b     (HMMA, bf16x3 split)
    gemm_mma<<<dim3(20, 4), 256>>>(BF + BO_FEATS, 2560L*2048, BF + BO_FW, 512L*2048,
                                   x, CH, 2560, CH, CDF, feat_b, nullptr);
    split_bf16<<<sgrid(2560L*512), 256>>>(x, 512, 2560, 512, BF + BO_X, 2560L*512, 2560L*512);

    // encoder input-gate precompute
    gemm_mma<<<dim3(20, 16), 256>>>(BF + BO_X, 2560L*512, BF + BO_WIF, 2048L*512,
                                    ginF, G4, 2560, G4, CH, bih_f, bhh_f);
    gemm_mma<<<dim3(20, 16), 256>>>(BF + BO_X, 2560L*512, BF + BO_WIB, 2048L*512,
                                    ginB, G4, 2560, G4, CH, bih_b, bhh_b);

    // forward + backward LSTMs (persistent)
    lstm_persist<<<128, 256>>>(Whh_f, ginF, (long)G4, CL * G4, nullptr, hz,
                               hF, (long)CB * CH, CH, cF, part, CL, +1);
    lstm_persist<<<128, 256>>>(Whh_b, ginB, (long)G4, CL * G4, nullptr, hz,
                               hB, (long)CB * CH, CH, cBb, part, CL, -1);

    // ctx[b] = sum_l enc[b,l,:]  (attention collapses: softmax over singleton axis)
    ctx_sum<<<256, 256>>>(hF, hB, ctx);

    // decoder input-gate precompute
    gather_emb<<<(CT * CB * CE) / 256, 256>>>(emb, targets, demb);
    split_bf16<<<sgrid(2560L*512), 256>>>(demb, 512, 2496, 512,
                                          BF + BO_DEMB, 2560L*512, 2560L*512);
    gemm_mma<<<dim3(20, 16), 256>>>(BF + BO_DEMB, 2560L*512, BF + BO_WID, 2048L*512,
                                    embW, G4, 2496, G4, CE, nullptr, nullptr);
    gemm_small64<<<dim3(64, 4), 256>>>(ctx, 2 * CH, Wih_d + CE, 2 * CH + CE, part, G4, 256);
    ctx_combine<<<512, 256>>>(part, bih_d, bhh_d, ctxW);

    // decoder LSTM persistent (hD layout [B][T][H])
    lstm_persist<<<128, 256>>>(Whh_d, embW, (long)CB * G4, G4, ctxW, hz,
                               hD, (long)CH, CT * CH, cD, part, CT, +1);

    // output projection: out[b,t,:] = hD[b,t,:] @ out_W^T + out_b  (HMMA)
    split_bf16<<<sgrid(2560L*512), 256>>>(hD, 512, 2496, 512, BF + BO_HD, 2560L*512, 2560L*512);
    gemm_mma<<<dim3(20, 157), 256>>>(BF + BO_HD, 2560L*512, BF + BO_WOUT, 20096L*512,
                                     out, CV, 2496, CV, CH, out_b, nullptr);
}

// round 11
// speedup vs baseline: 1.7913x; 1.0005x over previous
#include <cuda_runtime.h>
#include <cuda_bf16.h>
#include <math.h>
#include <stdint.h>

// Problem dims
#define CB   64      // batch
#define CL   40      // seq len
#define CT   39      // decoder steps (L-1)
#define CH   512     // hidden
#define CDF  2048    // feature dim
#define CE   512     // embedding dim
#define CV   20000   // vocab
#define G4   2048    // 4*H

typedef unsigned long long u64;

// ---------------- fp32 scratch ----------------
constexpr int OFF_X    = 0;
constexpr int OFF_GINF = OFF_X    + CB*CL*CH;
constexpr int OFF_GINB = OFF_GINF + CB*CL*G4;
constexpr int OFF_HF   = OFF_GINB + CB*CL*G4;
constexpr int OFF_HB   = OFF_HF   + CL*CB*CH;
constexpr int OFF_HD   = OFF_HB   + CL*CB*CH;     // hD layout [B][T][H] contiguous 2496x512
constexpr int OFF_CF   = OFF_HD   + CB*CT*CH;
constexpr int OFF_CB2  = OFF_CF   + CB*CH;
constexpr int OFF_CD   = OFF_CB2  + CB*CH;
constexpr int OFF_HZ   = OFF_CD   + CB*CH;
constexpr int OFF_CTX  = OFF_HZ   + CB*CH;
constexpr int OFF_DEMB = OFF_CTX  + CB*2*CH;
constexpr int OFF_EMBW = OFF_DEMB + CT*CB*CE;
constexpr int OFF_CTXW = OFF_EMBW + CT*CB*G4;
constexpr int OFF_PART = OFF_CTXW + CB*G4;
constexpr int SCRATCH_TOTAL = OFF_PART + 4*CB*G4;
__device__ __align__(256) float g_scratch[SCRATCH_TOTAL];
__device__ unsigned g_bar = 0;

// ---------------- bf16 hi/lo scratch (hi at off, lo at off + size) ----------------
constexpr long BO_WOUT  = 0;                               // 20096 x 512 (pad of 20000)
constexpr long BO_FW    = BO_WOUT  + 2L*20096*512;         // 512 x 2048
constexpr long BO_WIF   = BO_FW    + 2L*512*2048;          // 2048 x 512
constexpr long BO_WIB   = BO_WIF   + 2L*2048*512;
constexpr long BO_WID   = BO_WIB   + 2L*2048*512;          // 2048 x 512 (first E cols)
constexpr long BO_FEATS = BO_WID   + 2L*2048*512;          // 2560 x 2048
constexpr long BO_X     = BO_FEATS + 2L*2560*2048;         // 2560 x 512
constexpr long BO_DEMB  = BO_X     + 2L*2560*512;          // 2560 x 512 (pad of 2496)
constexpr long BO_HD    = BO_DEMB  + 2L*2560*512;          // 2560 x 512 (pad of 2496)
constexpr long BF_TOTAL = BO_HD    + 2L*2560*512;
__device__ __align__(256) __nv_bfloat16 g_bf[BF_TOTAL];

// ---------------- helpers ----------------
__device__ __forceinline__ void fma2(u64 &d, u64 a, u64 b) {
    asm("fma.rn.f32x2 %0, %1, %2, %0;" : "+l"(d) : "l"(a), "l"(b));
}
__device__ __forceinline__ float pairsum(u64 v) {
    float lo = __uint_as_float((unsigned)(v & 0xffffffffull));
    float hi = __uint_as_float((unsigned)(v >> 32));
    return lo + hi;
}
__device__ __forceinline__ void sts4(float* dst, float4 v) {
    *reinterpret_cast<float2*>(dst)     = make_float2(v.x, v.y);
    *reinterpret_cast<float2*>(dst + 2) = make_float2(v.z, v.w);
}
__device__ __forceinline__ uint32_t smem_u32(const void* p) {
    uint32_t a;
    asm("{ .reg .u64 t; cvta.to.shared.u64 t, %1; cvt.u32.u64 %0, t; }" : "=r"(a) : "l"(p));
    return a;
}
__device__ __forceinline__ void cp16(uint32_t dst, const void* src) {
    asm volatile("cp.async.cg.shared.global [%0], [%1], 16;" :: "r"(dst), "l"(src) : "memory");
}
__device__ __forceinline__ void cp_commit_wait0() {
    asm volatile("cp.async.commit_group;" ::: "memory");
    asm volatile("cp.async.wait_group 0;" ::: "memory");
}
__device__ __forceinline__ void ldsm4(uint32_t* r, uint32_t addr) {
    asm volatile("ldmatrix.sync.aligned.m8n8.x4.shared.b16 {%0,%1,%2,%3}, [%4];"
                 : "=r"(r[0]), "=r"(r[1]), "=r"(r[2]), "=r"(r[3]) : "r"(addr));
}
__device__ __forceinline__ void mma16816(float* d, const uint32_t* a, const uint32_t* b) {
    asm volatile("mma.sync.aligned.m16n8k16.row.col.f32.bf16.bf16.f32 "
                 "{%0,%1,%2,%3}, {%4,%5,%6,%7}, {%8,%9}, {%0,%1,%2,%3};"
                 : "+f"(d[0]), "+f"(d[1]), "+f"(d[2]), "+f"(d[3])
                 : "r"(a[0]), "r"(a[1]), "r"(a[2]), "r"(a[3]), "r"(b[0]), "r"(b[1]));
}
// swizzled element index for (row r, k-chunk c) in a [128][32] bf16 tile; 8 elems/chunk.
__device__ __forceinline__ int swzi(int r, int c) {
    int cc = (c + r + (r >> 2)) & 3;
    return r * 32 + cc * 8;
}

// ---------------- grid barrier (128 resident blocks) ----------------
__device__ __forceinline__ void grid_bar(unsigned &target) {
    __syncthreads();
    target += 128u;
    if (threadIdx.x == 0) {
        __threadfence();
        atomicAdd(&g_bar, 1u);
        unsigned v;
        do {
            asm volatile("ld.volatile.global.u32 %0, [%1];" : "=r"(v) : "l"(&g_bar));
        } while (v < target);
        __threadfence();
    }
    __syncthreads();
}
__device__ __forceinline__ void grid_bar_final(unsigned target) {
    __syncthreads();
    if (threadIdx.x == 0) {
        __threadfence();
        unsigned old = atomicAdd(&g_bar, 1u);
        if (old == target + 127u) {
            __threadfence();
            asm volatile("st.volatile.global.u32 [%0], %1;" :: "l"(&g_bar), "r"(0u));
        }
    }
}

// ================= split fp32 -> bf16 hi/lo (with row padding to zeros) ============
__global__ void split_bf16(const float* __restrict__ src, int ld, int rows_valid, int cols,
                           __nv_bfloat16* __restrict__ hi, long losz, long total)
{
    long idx = (long)blockIdx.x * 256 + threadIdx.x;
    if (idx >= total) return;
    long r = idx / cols;
    int  c = (int)(idx - r * cols);
    float v = (r < rows_valid) ? src[r * (long)ld + c] : 0.f;
    __nv_bfloat16 h = __float2bfloat16(v);
    float rem = v - __bfloat162float(h);
    hi[idx]        = h;
    hi[idx + losz] = __float2bfloat16(rem);
}

// ================= HMMA GEMM: C[M,N] = A[M,K] * W[N,K]^T (+b0+b1) ==============
// A,W as bf16 hi (lo at +size), row-major, rows padded to tile multiples.
// 128x128 tile, BK=32, 8 warps (2m x 4n), warp tile 64x32. bf16x3 split accuracy.
__global__ __launch_bounds__(256) void gemm_mma(
    const __nv_bfloat16* __restrict__ Ah, long Asz,
    const __nv_bfloat16* __restrict__ Wh, long Wsz,
    float* __restrict__ C, int ldc, int Mvalid, int N, int K,
    const float* __restrict__ bias0, const float* __restrict__ bias1)
{
    __shared__ __align__(128) __nv_bfloat16 sAh[128 * 32];
    __shared__ __align__(128) __nv_bfloat16 sAl[128 * 32];
    __shared__ __align__(128) __nv_bfloat16 sWh[128 * 32];
    __shared__ __align__(128) __nv_bfloat16 sWl[128 * 32];

    const int tid  = threadIdx.x;
    const int wid  = tid >> 5, lane = tid & 31;
    const int wm   = wid >> 2;          // 0..1  (64 rows each)
    const int wn   = wid & 3;           // 0..3  (32 cols each)
    const int m0   = blockIdx.x * 128, n0 = blockIdx.y * 128;

    const __nv_bfloat16* Al = Ah + Asz;
    const __nv_bfloat16* Wl = Wh + Wsz;

    const uint32_t bAh = smem_u32(sAh), bAl = smem_u32(sAl);
    const uint32_t bWh = smem_u32(sWh), bWl = smem_u32(sWl);

    float acc[4][4][4];
#pragma unroll
    for (int i = 0; i < 4; i++)
#pragma unroll
        for (int j = 0; j < 4; j++)
#pragma unroll
            for (int q = 0; q < 4; q++) acc[i][j][q] = 0.f;

    // per-lane ldmatrix address components
    const int a_r  = lane & 15;                       // row within 16
    const int a_cg = lane >> 4;                       // k-chunk half (0..1)
    const int b_r  = (lane & 7) + ((lane >> 4) << 3); // row within 16 (n)
    const int b_cg = (lane >> 3) & 1;                 // k-chunk half

    const int nch = K >> 5;
    for (int c = 0; c < nch; c++) {
        const int k0 = c << 5;
        // ---- fill 4 tiles via cp.async (swizzled) ----
#pragma unroll
        for (int g = 0; g < 2; g++) {
            int u  = tid + 256 * g;
            int r  = u >> 2, cc = u & 3;
            uint32_t so = (uint32_t)swzi(r, cc) * 2;
            long ga = (long)(m0 + r) * K + k0 + cc * 8;
            long gb = (long)(n0 + r) * K + k0 + cc * 8;
            cp16(bAh + so, Ah + ga);
            cp16(bAl + so, Al + ga);
            cp16(bWh + so, Wh + gb);
            cp16(bWl + so, Wl + gb);
        }
        cp_commit_wait0();
        __syncthreads();

        // ---- compute: two k16 steps ----
#pragma unroll
        for (int h = 0; h < 2; h++) {
            uint32_t ah[4][4], al[4][4];
#pragma unroll
            for (int t = 0; t < 4; t++) {
                int r  = wm * 64 + t * 16 + a_r;
                int ch = 2 * h + a_cg;
                uint32_t off = (uint32_t)swzi(r, ch) * 2;
                ldsm4(ah[t], bAh + off);
                ldsm4(al[t], bAl + off);
            }
            uint32_t bh[4][2], bl[4][2];
#pragma unroll
            for (int p = 0; p < 2; p++) {
                int r  = wn * 32 + p * 16 + b_r;
                int ch = 2 * h + b_cg;
                uint32_t off = (uint32_t)swzi(r, ch) * 2;
                uint32_t tmp[4];
                ldsm4(tmp, bWh + off);
                bh[2*p][0] = tmp[0]; bh[2*p][1] = tmp[1];
                bh[2*p+1][0] = tmp[2]; bh[2*p+1][1] = tmp[3];
                ldsm4(tmp, bWl + off);
                bl[2*p][0] = tmp[0]; bl[2*p][1] = tmp[1];
                bl[2*p+1][0] = tmp[2]; bl[2*p+1][1] = tmp[3];
            }
#pragma unroll
            for (int t = 0; t < 4; t++)
#pragma unroll
                for (int n = 0; n < 4; n++) {
                    mma16816(acc[t][n], ah[t], bh[n]);
                    mma16816(acc[t][n], ah[t], bl[n]);
                    mma16816(acc[t][n], al[t], bh[n]);
                }
        }
        __syncthreads();
    }

    // ---- epilogue ----
#pragma unroll
    for (int t = 0; t < 4; t++) {
#pragma unroll
        for (int n = 0; n < 4; n++) {
            int row = m0 + wm * 64 + t * 16 + (lane >> 2);
            int col = n0 + wn * 32 + n * 8 + 2 * (lane & 3);
            if (col < N) {
                float bx = 0.f, by = 0.f;
                if (bias0) { bx += bias0[col]; by += bias0[col + 1]; }
                if (bias1) { bx += bias1[col]; by += bias1[col + 1]; }
                if (row < Mvalid)
                    *reinterpret_cast<float2*>(C + (long)row * ldc + col) =
                        make_float2(acc[t][n][0] + bx, acc[t][n][1] + by);
                if (row + 8 < Mvalid)
                    *reinterpret_cast<float2*>(C + (long)(row + 8) * ldc + col) =
                        make_float2(acc[t][n][2] + bx, acc[t][n][3] + by);
            }
        }
    }
}

// ---------------- small-M GEMM (used once for ctx @ Wih_d[:,E:]) ----------------
__global__ __launch_bounds__(256) void gemm_small64(
    const float* __restrict__ A, int lda,
    const float* __restrict__ W, int ldw,
    float* __restrict__ P, int N, int Kps)
{
    __shared__ float As[64][34];
    __shared__ float Ws[32][34];
    const int tid  = threadIdx.x;
    const int n0   = blockIdx.x * 32;
    const int kb   = blockIdx.y * Kps;
    const int tm   = tid >> 4;
    const int tn   = tid & 15;
    const int lrow = tid >> 3;
    const int lcol = (tid & 7) << 2;

    u64 acc[4][2];
#pragma unroll
    for (int i = 0; i < 4; i++) { acc[i][0] = 0ull; acc[i][1] = 0ull; }

    const int nk = Kps >> 5;
    float4 pa0, pa1, pw;
    {
        int k = kb + lcol;
        pa0 = *reinterpret_cast<const float4*>(A + (long)lrow * lda + k);
        pa1 = *reinterpret_cast<const float4*>(A + (long)(lrow + 32) * lda + k);
        pw  = *reinterpret_cast<const float4*>(W + (long)(n0 + lrow) * ldw + k);
    }
    for (int c = 0; c < nk; c++) {
        sts4(&As[lrow][lcol],      pa0);
        sts4(&As[lrow + 32][lcol], pa1);
        sts4(&Ws[lrow][lcol],      pw);
        __syncthreads();
        if (c + 1 < nk) {
            int k = kb + ((c + 1) << 5) + lcol;
            pa0 = *reinterpret_cast<const float4*>(A + (long)lrow * lda + k);
            pa1 = *reinterpret_cast<const float4*>(A + (long)(lrow + 32) * lda + k);
            pw  = *reinterpret_cast<const float4*>(W + (long)(n0 + lrow) * ldw + k);
        }
#pragma unroll
        for (int kk = 0; kk < 16; kk++) {
            u64 a2[4], w2[2];
#pragma unroll
            for (int i = 0; i < 4; i++)
                a2[i] = *reinterpret_cast<const u64*>(&As[tm + 16 * i][kk << 1]);
#pragma unroll
            for (int j = 0; j < 2; j++)
                w2[j] = *reinterpret_cast<const u64*>(&Ws[tn + 16 * j][kk << 1]);
#pragma unroll
            for (int i = 0; i < 4; i++)
#pragma unroll
                for (int j = 0; j < 2; j++) fma2(acc[i][j], a2[i], w2[j]);
        }
        __syncthreads();
    }
    float* out = P + (long)blockIdx.y * 64 * N;
#pragma unroll
    for (int i = 0; i < 4; i++)
#pragma unroll
        for (int j = 0; j < 2; j++)
            out[(tm + 16 * i) * (long)N + n0 + tn + 16 * j] = pairsum(acc[i][j]);
}

// ---------------- persistent LSTM (step GEMM + fused gates, grid barriers) --------
__device__ __forceinline__ void step_gemm(const float* __restrict__ A, int lda,
                                          const float* __restrict__ W,
                                          float* __restrict__ part, int bx)
{
    __shared__ float As[64][34];
    __shared__ float Ws[32][34];
    const int tid  = threadIdx.x;
    const int n0   = (bx & 63) * 32;
    const int kb   = (bx >> 6) * 256;
    const int tm   = tid >> 4;
    const int tn   = tid & 15;
    const int lrow = tid >> 3;
    const int lcol = (tid & 7) << 2;

    u64 acc[4][2];
#pragma unroll
    for (int i = 0; i < 4; i++) { acc[i][0] = 0ull; acc[i][1] = 0ull; }

    float4 pa0, pa1, pw;
    {
        int k = kb + lcol;
        pa0 = *reinterpret_cast<const float4*>(A + (long)lrow * lda + k);
        pa1 = *reinterpret_cast<const float4*>(A + (long)(lrow + 32) * lda + k);
        pw  = *reinterpret_cast<const float4*>(W + (long)(n0 + lrow) * CH + k);
    }
    for (int c = 0; c < 8; c++) {
        sts4(&As[lrow][lcol],      pa0);
        sts4(&As[lrow + 32][lcol], pa1);
        sts4(&Ws[lrow][lcol],      pw);
        __syncthreads();
        if (c < 7) {
            int k = kb + ((c + 1) << 5) + lcol;
            pa0 = *reinterpret_cast<const float4*>(A + (long)lrow * lda + k);
            pa1 = *reinterpret_cast<const float4*>(A + (long)(lrow + 32) * lda + k);
            pw  = *reinterpret_cast<const float4*>(W + (long)(n0 + lrow) * CH + k);
        }
#pragma unroll
        for (int kk = 0; kk < 16; kk++) {
            u64 a2[4], w2[2];
#pragma unroll
            for (int i = 0; i < 4; i++)
                a2[i] = *reinterpret_cast<const u64*>(&As[tm + 16 * i][kk << 1]);
#pragma unroll
            for (int j = 0; j < 2; j++)
                w2[j] = *reinterpret_cast<const u64*>(&Ws[tn + 16 * j][kk << 1]);
#pragma unroll
            for (int i = 0; i < 4; i++)
#pragma unroll
                for (int j = 0; j < 2; j++) fma2(acc[i][j], a2[i], w2[j]);
        }
        __syncthreads();
    }
    float* out = part + (long)(bx >> 6) * 64 * G4;
#pragma unroll
    for (int i = 0; i < 4; i++)
#pragma unroll
        for (int j = 0; j < 2; j++)
            out[(tm + 16 * i) * G4 + n0 + tn + 16 * j] = pairsum(acc[i][j]);
}

__device__ __forceinline__ void gates_fn(const float* P, const float* D1, int ldd1,
                                         const float* D2, float* c,
                                         float* h_out, int h_ld, int idx)
{
    int b = idx >> 9, u = idx & 511;
    const float* g0 = P + (long)b * G4;
    const float* g1 = P + (long)CB * G4 + (long)b * G4;
    const float* d1 = D1 + (long)b * ldd1;
    float gi = g0[u]        + g1[u]        + d1[u];
    float gf = g0[512 + u]  + g1[512 + u]  + d1[512 + u];
    float gg = g0[1024 + u] + g1[1024 + u] + d1[1024 + u];
    float go = g0[1536 + u] + g1[1536 + u] + d1[1536 + u];
    if (D2) {
        const float* d2 = D2 + (long)b * G4;
        gi += d2[u]; gf += d2[512 + u]; gg += d2[1024 + u]; go += d2[1536 + u];
    }
    float i_ = 1.f / (1.f + expf(-gi));
    float f_ = 1.f / (1.f + expf(-gf));
    float g_ = tanhf(gg);
    float o_ = 1.f / (1.f + expf(-go));
    float cn = f_ * c[idx] + i_ * g_;
    c[idx] = cn;
    h_out[(long)b * h_ld + u] = o_ * tanhf(cn);
}

__global__ __launch_bounds__(256) void lstm_persist(
    const float* __restrict__ Whh,
    const float* __restrict__ gin, long gin_step, int gin_ld,
    const float* __restrict__ D2,
    const float* __restrict__ hz,
    float* __restrict__ hbase, long h_step, int h_ld,
    float* __restrict__ c, float* __restrict__ part,
    int nsteps, int dir)
{
    unsigned target = 0;
    const int bx = blockIdx.x;
    const int idx = bx * 256 + threadIdx.x;
    for (int s = 0; s < nsteps; s++) {
        int l = (dir > 0) ? s : (nsteps - 1 - s);
        const float* hin; int hlda;
        if (s == 0) { hin = hz; hlda = CH; }
        else {
            int lp = (dir > 0) ? (l - 1) : (l + 1);
            hin = hbase + (long)lp * h_step; hlda = h_ld;
        }
        step_gemm(hin, hlda, Whh, part, bx);
        grid_bar(target);
        gates_fn(part, gin + (long)l * gin_step, gin_ld, D2, c,
                 hbase + (long)l * h_step, h_ld, idx);
        if (s + 1 < nsteps) grid_bar(target);
        else                grid_bar_final(target);
    }
}

// ---------------- small elementwise kernels ----------------
__global__ void zero_state(float* cF, float* cB, float* cD, float* hz)
{
    int idx = blockIdx.x * blockDim.x + threadIdx.x;
    cF[idx] = 0.f; cB[idx] = 0.f; cD[idx] = 0.f; hz[idx] = 0.f;
}

__global__ void ctx_sum(const float* __restrict__ hF, const float* __restrict__ hB,
                        float* __restrict__ ctx)
{
    int idx = blockIdx.x * blockDim.x + threadIdx.x;  // 64*1024
    int b = idx >> 10, j = idx & 1023;
    float s = 0.f;
    if (j < 512) {
        for (int l = 0; l < CL; l++) s += hF[((long)l * CB + b) * CH + j];
    } else {
        int j2 = j - 512;
        for (int l = 0; l < CL; l++) s += hB[((long)l * CB + b) * CH + j2];
    }
    ctx[idx] = s;
}

__global__ void ctx_combine(const float* __restrict__ P,
                            const float* __restrict__ b0,
                            const float* __restrict__ b1,
                            float* __restrict__ ctxW)
{
    int idx = blockIdx.x * blockDim.x + threadIdx.x;  // 64*2048
    int b = idx >> 11, n = idx & 2047;
    float s = b0[n] + b1[n];
#pragma unroll
    for (int z = 0; z < 4; z++) s += P[((long)z * CB + b) * G4 + n];
    ctxW[idx] = s;
}

__global__ void gather_emb(const float* __restrict__ emb, const int* __restrict__ targets,
                           float* __restrict__ dst)
{
    int idx = blockIdx.x * blockDim.x + threadIdx.x;  // 39*64*512
    int e = idx & 511;
    int r = idx >> 9;
    int t = r / CB, b = r - t * CB;
    int tgt = targets[b * CL + t];
    dst[idx] = emb[(long)tgt * CE + e];
}

// ---------------- launch ----------------
static inline int sgrid(long n) { return (int)((n + 255) / 256); }

extern "C" void kernel_launch(void* const* d_in, const int* in_sizes, int n_in,
                              void* d_out, int out_size)
{
    (void)in_sizes; (void)n_in; (void)out_size;
    const float* feats  = (const float*)d_in[0];
    const float* feat_W = (const float*)d_in[1];
    const float* feat_b = (const float*)d_in[2];
    const float* Wih_f  = (const float*)d_in[3];
    const float* Whh_f  = (const float*)d_in[4];
    const float* bih_f  = (const float*)d_in[5];
    const float* bhh_f  = (const float*)d_in[6];
    const float* Wih_b  = (const float*)d_in[7];
    const float* Whh_b  = (const float*)d_in[8];
    const float* bih_b  = (const float*)d_in[9];
    const float* bhh_b  = (const float*)d_in[10];
    const float* emb    = (const float*)d_in[11];
    const float* Wih_d  = (const float*)d_in[12];
    const float* Whh_d  = (const float*)d_in[13];
    const float* bih_d  = (const float*)d_in[14];
    const float* bhh_d  = (const float*)d_in[15];
    // d_in[16..20]: attention params — provably unused (softmax over singleton axis -> ones)
    const float* out_W  = (const float*)d_in[21];
    const float* out_b  = (const float*)d_in[22];
    const int*   targets = (const int*)d_in[23];
    float* out = (float*)d_out;

    float* S = nullptr;
    cudaGetSymbolAddress((void**)&S, g_scratch);
    __nv_bfloat16* BF = nullptr;
    cudaGetSymbolAddress((void**)&BF, g_bf);

    float* x     = S + OFF_X;
    float* ginF  = S + OFF_GINF;
    float* ginB  = S + OFF_GINB;
    float* hF    = S + OFF_HF;
    float* hB    = S + OFF_HB;
    float* hD    = S + OFF_HD;
    float* cF    = S + OFF_CF;
    float* cBb   = S + OFF_CB2;
    float* cD    = S + OFF_CD;
    float* hz    = S + OFF_HZ;
    float* ctx   = S + OFF_CTX;
    float* demb  = S + OFF_DEMB;
    float* embW  = S + OFF_EMBW;
    float* ctxW  = S + OFF_CTXW;
    float* part  = S + OFF_PART;

    zero_state<<<128, 256>>>(cF, cBb, cD, hz);

    // ---- weight/input splits to bf16 hi/lo ----
    split_bf16<<<sgrid(20096L*512), 256>>>(out_W, 512, 20000, 512,
                                           BF + BO_WOUT, 20096L*512, 20096L*512);
    split_bf16<<<sgrid(512L*2048), 256>>>(feat_W, 2048, 512, 2048,
                                          BF + BO_FW, 512L*2048, 512L*2048);
    split_bf16<<<sgrid(2048L*512), 256>>>(Wih_f, 512, 2048, 512,
                                          BF + BO_WIF, 2048L*512, 2048L*512);
    split_bf16<<<sgrid(2048L*512), 256>>>(Wih_b, 512, 2048, 512,
                                          BF + BO_WIB, 2048L*512, 2048L*512);
    split_bf16<<<sgrid(2048L*512), 256>>>(Wih_d, 2*CH + CE, 2048, 512,
                                          BF + BO_WID, 2048L*512, 2048L*512);
    split_bf16<<<sgrid(2560L*2048), 256>>>(feats, 2048, 2560, 2048,
                                           BF + BO_FEATS, 2560L*2048, 2560L*2048);

    // x = feats @ feat_W^T + feat_b     (HMMA, bf16x3 split)
    gemm_mma<<<dim3(20, 4), 256>>>(BF + BO_FEATS, 2560L*2048, BF + BO_FW, 512L*2048,
                                   x, CH, 2560, CH, CDF, feat_b, nullptr);
    split_bf16<<<sgrid(2560L*512), 256>>>(x, 512, 2560, 512, BF + BO_X, 2560L*512, 2560L*512);

    // encoder input-gate precompute
    gemm_mma<<<dim3(20, 16), 256>>>(BF + BO_X, 2560L*512, BF + BO_WIF, 2048L*512,
                                    ginF, G4, 2560, G4, CH, bih_f, bhh_f);
    gemm_mma<<<dim3(20, 16), 256>>>(BF + BO_X, 2560L*512, BF + BO_WIB, 2048L*512,
                                    ginB, G4, 2560, G4, CH, bih_b, bhh_b);

    // forward + backward LSTMs (persistent)
    lstm_persist<<<128, 256>>>(Whh_f, ginF, (long)G4, CL * G4, nullptr, hz,
                               hF, (long)CB * CH, CH, cF, part, CL, +1);
    lstm_persist<<<128, 256>>>(Whh_b, ginB, (long)G4, CL * G4, nullptr, hz,
                               hB, (long)CB * CH, CH, cBb, part, CL, -1);

    // ctx[b] = sum_l enc[b,l,:]  (attention collapses: softmax over singleton axis)
    ctx_sum<<<256, 256>>>(hF, hB, ctx);

    // decoder input-gate precompute
    gather_emb<<<(CT * CB * CE) / 256, 256>>>(emb, targets, demb);
    split_bf16<<<sgrid(2560L*512), 256>>>(demb, 512, 2496, 512,
                                          BF + BO_DEMB, 2560L*512, 2560L*512);
    gemm_mma<<<dim3(20, 16), 256>>>(BF + BO_DEMB, 2560L*512, BF + BO_WID, 2048L*512,
                                    embW, G4, 2496, G4, CE, nullptr, nullptr);
    gemm_small64<<<dim3(64, 4), 256>>>(ctx, 2 * CH, Wih_d + CE, 2 * CH + CE, part, G4, 256);
    ctx_combine<<<512, 256>>>(part, bih_d, bhh_d, ctxW);

    // decoder LSTM persistent (hD layout [B][T][H])
    lstm_persist<<<128, 256>>>(Whh_d, embW, (long)CB * G4, G4, ctxW, hz,
                               hD, (long)CH, CT * CH, cD, part, CT, +1);

    // output projection: out[b,t,:] = hD[b,t,:] @ out_W^T + out_b  (HMMA)
    split_bf16<<<sgrid(2560L*512), 256>>>(hD, 512, 2496, 512, BF + BO_HD, 2560L*512, 2560L*512);
    gemm_mma<<<dim3(20, 157), 256>>>(BF + BO_HD, 2560L*512, BF + BO_WOUT, 20096L*512,
                                     out, CV, 2496, CV, CH, out_b, nullptr);
}

// round 12
// speedup vs baseline: 1.8409x; 1.0277x over previous
#include <cuda_runtime.h>
#include <cuda_bf16.h>
#include <math.h>
#include <stdint.h>

// Problem dims
#define CB   64      // batch
#define CL   40      // seq len
#define CT   39      // decoder steps (L-1)
#define CH   512     // hidden
#define CDF  2048    // feature dim
#define CE   512     // embedding dim
#define CV   20000   // vocab
#define G4   2048    // 4*H

typedef unsigned long long u64;

// ---------------- fp32 scratch ----------------
constexpr int OFF_X    = 0;
constexpr int OFF_GINF = OFF_X    + CB*CL*CH;
constexpr int OFF_GINB = OFF_GINF + CB*CL*G4;
constexpr int OFF_HF   = OFF_GINB + CB*CL*G4;
constexpr int OFF_HB   = OFF_HF   + CL*CB*CH;
constexpr int OFF_HD   = OFF_HB   + CL*CB*CH;     // hD layout [B][T][H] contiguous 2496x512
constexpr int OFF_CF   = OFF_HD   + CB*CT*CH;
constexpr int OFF_CB2  = OFF_CF   + CB*CH;
constexpr int OFF_CD   = OFF_CB2  + CB*CH;
constexpr int OFF_HZ   = OFF_CD   + CB*CH;
constexpr int OFF_CTX  = OFF_HZ   + CB*CH;
constexpr int OFF_DEMB = OFF_CTX  + CB*2*CH;
constexpr int OFF_EMBW = OFF_DEMB + CT*CB*CE;
constexpr int OFF_CTXW = OFF_EMBW + CT*CB*G4;
constexpr int OFF_PART = OFF_CTXW + CB*G4;
constexpr int SCRATCH_TOTAL = OFF_PART + 4*CB*G4;
__device__ __align__(256) float g_scratch[SCRATCH_TOTAL];
__device__ unsigned g_bar = 0;

// ---------------- bf16 hi/lo scratch (hi at off, lo at off + size) ----------------
constexpr long BO_WOUT  = 0;                               // 20096 x 512 (pad of 20000)
constexpr long BO_FW    = BO_WOUT  + 2L*20096*512;         // 512 x 2048
constexpr long BO_WIF   = BO_FW    + 2L*512*2048;          // 2048 x 512
constexpr long BO_WIB   = BO_WIF   + 2L*2048*512;
constexpr long BO_WID   = BO_WIB   + 2L*2048*512;          // 2048 x 512 (first E cols)
constexpr long BO_FEATS = BO_WID   + 2L*2048*512;          // 2560 x 2048
constexpr long BO_X     = BO_FEATS + 2L*2560*2048;         // 2560 x 512
constexpr long BO_DEMB  = BO_X     + 2L*2560*512;          // 2560 x 512 (pad of 2496)
constexpr long BO_HD    = BO_DEMB  + 2L*2560*512;          // 2560 x 512 (pad of 2496)
constexpr long BF_TOTAL = BO_HD    + 2L*2560*512;
__device__ __align__(256) __nv_bfloat16 g_bf[BF_TOTAL];

// ---------------- helpers ----------------
__device__ __forceinline__ void fma2(u64 &d, u64 a, u64 b) {
    asm("fma.rn.f32x2 %0, %1, %2, %0;" : "+l"(d) : "l"(a), "l"(b));
}
__device__ __forceinline__ float pairsum(u64 v) {
    float lo = __uint_as_float((unsigned)(v & 0xffffffffull));
    float hi = __uint_as_float((unsigned)(v >> 32));
    return lo + hi;
}
__device__ __forceinline__ void sts4(float* dst, float4 v) {
    *reinterpret_cast<float2*>(dst)     = make_float2(v.x, v.y);
    *reinterpret_cast<float2*>(dst + 2) = make_float2(v.z, v.w);
}
__device__ __forceinline__ uint32_t smem_u32(const void* p) {
    uint32_t a;
    asm("{ .reg .u64 t; cvta.to.shared.u64 t, %1; cvt.u32.u64 %0, t; }" : "=r"(a) : "l"(p));
    return a;
}
__device__ __forceinline__ void cp16(uint32_t dst, const void* src) {
    asm volatile("cp.async.cg.shared.global [%0], [%1], 16;" :: "r"(dst), "l"(src) : "memory");
}
__device__ __forceinline__ void cp_commit() {
    asm volatile("cp.async.commit_group;" ::: "memory");
}
__device__ __forceinline__ void cp_wait0() {
    asm volatile("cp.async.wait_group 0;" ::: "memory");
}
__device__ __forceinline__ void cp_wait1() {
    asm volatile("cp.async.wait_group 1;" ::: "memory");
}
__device__ __forceinline__ void ldsm4(uint32_t* r, uint32_t addr) {
    asm volatile("ldmatrix.sync.aligned.m8n8.x4.shared.b16 {%0,%1,%2,%3}, [%4];"
                 : "=r"(r[0]), "=r"(r[1]), "=r"(r[2]), "=r"(r[3]) : "r"(addr));
}
__device__ __forceinline__ void mma16816(float* d, const uint32_t* a, const uint32_t* b) {
    asm volatile("mma.sync.aligned.m16n8k16.row.col.f32.bf16.bf16.f32 "
                 "{%0,%1,%2,%3}, {%4,%5,%6,%7}, {%8,%9}, {%0,%1,%2,%3};"
                 : "+f"(d[0]), "+f"(d[1]), "+f"(d[2]), "+f"(d[3])
                 : "r"(a[0]), "r"(a[1]), "r"(a[2]), "r"(a[3]), "r"(b[0]), "r"(b[1]));
}
// swizzled element index for (row r, k-chunk c) in a [128][32] bf16 tile; 8 elems/chunk.
__device__ __forceinline__ int swzi(int r, int c) {
    int cc = (c + r + (r >> 2)) & 3;
    return r * 32 + cc * 8;
}

// ---------------- grid barrier (128 resident blocks) ----------------
__device__ __forceinline__ void grid_bar(unsigned &target) {
    __syncthreads();
    target += 128u;
    if (threadIdx.x == 0) {
        __threadfence();
        atomicAdd(&g_bar, 1u);
        unsigned v;
        do {
            asm volatile("ld.volatile.global.u32 %0, [%1];" : "=r"(v) : "l"(&g_bar));
        } while (v < target);
        __threadfence();
    }
    __syncthreads();
}
__device__ __forceinline__ void grid_bar_final(unsigned target) {
    __syncthreads();
    if (threadIdx.x == 0) {
        __threadfence();
        unsigned old = atomicAdd(&g_bar, 1u);
        if (old == target + 127u) {
            __threadfence();
            asm volatile("st.volatile.global.u32 [%0], %1;" :: "l"(&g_bar), "r"(0u));
        }
    }
}

// ================= split fp32 -> bf16 hi/lo (with row padding to zeros) ============
__global__ void split_bf16(const float* __restrict__ src, int ld, int rows_valid, int cols,
                           __nv_bfloat16* __restrict__ hi, long losz, long total)
{
    long idx = (long)blockIdx.x * 256 + threadIdx.x;
    if (idx >= total) return;
    long r = idx / cols;
    int  c = (int)(idx - r * cols);
    float v = (r < rows_valid) ? src[r * (long)ld + c] : 0.f;
    __nv_bfloat16 h = __float2bfloat16(v);
    float rem = v - __bfloat162float(h);
    hi[idx]        = h;
    hi[idx + losz] = __float2bfloat16(rem);
}

// ================= HMMA GEMM (double-buffered): C = A * W^T (+b0+b1) ==============
// A,W as bf16 hi (lo at +size), row-major, rows padded to tile multiples.
// 128x128 tile, BK=32, 8 warps (2m x 4n), warp tile 64x32. bf16x3 split accuracy.
// dyn smem: 2 stages x (Ah|Al|Wh|Wl) x 8KB = 64KB.
constexpr int MMA_STAGE_B = 32768;          // bytes per stage
constexpr int MMA_SMEM    = 2 * MMA_STAGE_B;

__global__ __launch_bounds__(256) void gemm_mma(
    const __nv_bfloat16* __restrict__ Ah, long Asz,
    const __nv_bfloat16* __restrict__ Wh, long Wsz,
    float* __restrict__ C, int ldc, int Mvalid, int N, int K,
    const float* __restrict__ bias0, const float* __restrict__ bias1)
{
    extern __shared__ __align__(128) __nv_bfloat16 dynsmem[];
    const uint32_t base = smem_u32(dynsmem);

    const int tid  = threadIdx.x;
    const int wid  = tid >> 5, lane = tid & 31;
    const int wm   = wid >> 2;          // 0..1  (64 rows each)
    const int wn   = wid & 3;           // 0..3  (32 cols each)
    const int m0   = blockIdx.x * 128, n0 = blockIdx.y * 128;

    const __nv_bfloat16* Al = Ah + Asz;
    const __nv_bfloat16* Wl = Wh + Wsz;

    float acc[4][4][4];
#pragma unroll
    for (int i = 0; i < 4; i++)
#pragma unroll
        for (int j = 0; j < 4; j++)
#pragma unroll
            for (int q = 0; q < 4; q++) acc[i][j][q] = 0.f;

    // staging indices (fixed per thread)
    const int s_r0 = tid >> 2, s_c0 = tid & 3;           // g=0
    const int s_r1 = (tid + 256) >> 2, s_c1 = tid & 3;   // g=1
    const uint32_t so0 = (uint32_t)swzi(s_r0, s_c0) * 2;
    const uint32_t so1 = (uint32_t)swzi(s_r1, s_c1) * 2;

    // per-lane ldmatrix address components
    const int a_r  = lane & 15;                       // row within 16
    const int a_cg = lane >> 4;                       // k-chunk half (0..1)
    const int b_r  = (lane & 7) + ((lane >> 4) << 3); // row within 16 (n)
    const int b_cg = (lane >> 3) & 1;                 // k-chunk half

    const int nch = K >> 5;

    // ---- stage loader ----
    auto load_stage = [&](int c, uint32_t sb) {
        const int k0 = c << 5;
        long ga0 = (long)(m0 + s_r0) * K + k0 + s_c0 * 8;
        long gb0 = (long)(n0 + s_r0) * K + k0 + s_c0 * 8;
        cp16(sb +             so0, Ah + ga0);
        cp16(sb +  8192 +     so0, Al + ga0);
        cp16(sb + 16384 +     so0, Wh + gb0);
        cp16(sb + 24576 +     so0, Wl + gb0);
        long ga1 = (long)(m0 + s_r1) * K + k0 + s_c1 * 8;
        long gb1 = (long)(n0 + s_r1) * K + k0 + s_c1 * 8;
        cp16(sb +             so1, Ah + ga1);
        cp16(sb +  8192 +     so1, Al + ga1);
        cp16(sb + 16384 +     so1, Wh + gb1);
        cp16(sb + 24576 +     so1, Wl + gb1);
        cp_commit();
    };

    load_stage(0, base);

    for (int c = 0; c < nch; c++) {
        const uint32_t cb = base + (uint32_t)(c & 1) * MMA_STAGE_B;
        if (c + 1 < nch) {
            load_stage(c + 1, base + (uint32_t)((c + 1) & 1) * MMA_STAGE_B);
            cp_wait1();                 // wait only for stage c; c+1 stays in flight
        } else {
            cp_wait0();
        }
        __syncthreads();

        const uint32_t bAh = cb, bAl = cb + 8192, bWh = cb + 16384, bWl = cb + 24576;
#pragma unroll
        for (int h = 0; h < 2; h++) {
            uint32_t ah[4][4], al[4][4];
#pragma unroll
            for (int t = 0; t < 4; t++) {
                int r  = wm * 64 + t * 16 + a_r;
                int ch = 2 * h + a_cg;
                uint32_t off = (uint32_t)swzi(r, ch) * 2;
                ldsm4(ah[t], bAh + off);
                ldsm4(al[t], bAl + off);
            }
            uint32_t bh[4][2], bl[4][2];
#pragma unroll
            for (int p = 0; p < 2; p++) {
                int r  = wn * 32 + p * 16 + b_r;
                int ch = 2 * h + b_cg;
                uint32_t off = (uint32_t)swzi(r, ch) * 2;
                uint32_t tmp[4];
                ldsm4(tmp, bWh + off);
                bh[2*p][0] = tmp[0]; bh[2*p][1] = tmp[1];
                bh[2*p+1][0] = tmp[2]; bh[2*p+1][1] = tmp[3];
                ldsm4(tmp, bWl + off);
                bl[2*p][0] = tmp[0]; bl[2*p][1] = tmp[1];
                bl[2*p+1][0] = tmp[2]; bl[2*p+1][1] = tmp[3];
            }
#pragma unroll
            for (int t = 0; t < 4; t++)
#pragma unroll
                for (int n = 0; n < 4; n++) {
                    mma16816(acc[t][n], ah[t], bh[n]);
                    mma16816(acc[t][n], ah[t], bl[n]);
                    mma16816(acc[t][n], al[t], bh[n]);
                }
        }
        __syncthreads();   // all warps done with stage c before its buffer is refilled
    }

    // ---- epilogue ----
#pragma unroll
    for (int t = 0; t < 4; t++) {
#pragma unroll
        for (int n = 0; n < 4; n++) {
            int row = m0 + wm * 64 + t * 16 + (lane >> 2);
            int col = n0 + wn * 32 + n * 8 + 2 * (lane & 3);
            if (col < N) {
                float bx = 0.f, by = 0.f;
                if (bias0) { bx += bias0[col]; by += bias0[col + 1]; }
                if (bias1) { bx += bias1[col]; by += bias1[col + 1]; }
                if (row < Mvalid)
                    *reinterpret_cast<float2*>(C + (long)row * ldc + col) =
                        make_float2(acc[t][n][0] + bx, acc[t][n][1] + by);
                if (row + 8 < Mvalid)
                    *reinterpret_cast<float2*>(C + (long)(row + 8) * ldc + col) =
                        make_float2(acc[t][n][2] + bx, acc[t][n][3] + by);
            }
        }
    }
}

// ---------------- small-M GEMM (used once for ctx @ Wih_d[:,E:]) ----------------
__global__ __launch_bounds__(256) void gemm_small64(
    const float* __restrict__ A, int lda,
    const float* __restrict__ W, int ldw,
    float* __restrict__ P, int N, int Kps)
{
    __shared__ float As[64][34];
    __shared__ float Ws[32][34];
    const int tid  = threadIdx.x;
    const int n0   = blockIdx.x * 32;
    const int kb   = blockIdx.y * Kps;
    const int tm   = tid >> 4;
    const int tn   = tid & 15;
    const int lrow = tid >> 3;
    const int lcol = (tid & 7) << 2;

    u64 acc[4][2];
#pragma unroll
    for (int i = 0; i < 4; i++) { acc[i][0] = 0ull; acc[i][1] = 0ull; }

    const int nk = Kps >> 5;
    float4 pa0, pa1, pw;
    {
        int k = kb + lcol;
        pa0 = *reinterpret_cast<const float4*>(A + (long)lrow * lda + k);
        pa1 = *reinterpret_cast<const float4*>(A + (long)(lrow + 32) * lda + k);
        pw  = *reinterpret_cast<const float4*>(W + (long)(n0 + lrow) * ldw + k);
    }
    for (int c = 0; c < nk; c++) {
        sts4(&As[lrow][lcol],      pa0);
        sts4(&As[lrow + 32][lcol], pa1);
        sts4(&Ws[lrow][lcol],      pw);
        __syncthreads();
        if (c + 1 < nk) {
            int k = kb + ((c + 1) << 5) + lcol;
            pa0 = *reinterpret_cast<const float4*>(A + (long)lrow * lda + k);
            pa1 = *reinterpret_cast<const float4*>(A + (long)(lrow + 32) * lda + k);
            pw  = *reinterpret_cast<const float4*>(W + (long)(n0 + lrow) * ldw + k);
        }
#pragma unroll
        for (int kk = 0; kk < 16; kk++) {
            u64 a2[4], w2[2];
#pragma unroll
            for (int i = 0; i < 4; i++)
                a2[i] = *reinterpret_cast<const u64*>(&As[tm + 16 * i][kk << 1]);
#pragma unroll
            for (int j = 0; j < 2; j++)
                w2[j] = *reinterpret_cast<const u64*>(&Ws[tn + 16 * j][kk << 1]);
#pragma unroll
            for (int i = 0; i < 4; i++)
#pragma unroll
                for (int j = 0; j < 2; j++) fma2(acc[i][j], a2[i], w2[j]);
        }
        __syncthreads();
    }
    float* out = P + (long)blockIdx.y * 64 * N;
#pragma unroll
    for (int i = 0; i < 4; i++)
#pragma unroll
        for (int j = 0; j < 2; j++)
            out[(tm + 16 * i) * (long)N + n0 + tn + 16 * j] = pairsum(acc[i][j]);
}

// ---------------- persistent LSTM (step GEMM + fused gates, grid barriers) --------
__device__ __forceinline__ void step_gemm(const float* __restrict__ A, int lda,
                                          const float* __restrict__ W,
                                          float* __restrict__ part, int bx)
{
    __shared__ float As[64][34];
    __shared__ float Ws[32][34];
    const int tid  = threadIdx.x;
    const int n0   = (bx & 63) * 32;
    const int kb   = (bx >> 6) * 256;
    const int tm   = tid >> 4;
    const int tn   = tid & 15;
    const int lrow = tid >> 3;
    const int lcol = (tid & 7) << 2;

    u64 acc[4][2];
#pragma unroll
    for (int i = 0; i < 4; i++) { acc[i][0] = 0ull; acc[i][1] = 0ull; }

    float4 pa0, pa1, pw;
    {
        int k = kb + lcol;
        pa0 = *reinterpret_cast<const float4*>(A + (long)lrow * lda + k);
        pa1 = *reinterpret_cast<const float4*>(A + (long)(lrow + 32) * lda + k);
        pw  = *reinterpret_cast<const float4*>(W + (long)(n0 + lrow) * CH + k);
    }
    for (int c = 0; c < 8; c++) {
        sts4(&As[lrow][lcol],      pa0);
        sts4(&As[lrow + 32][lcol], pa1);
        sts4(&Ws[lrow][lcol],      pw);
        __syncthreads();
        if (c < 7) {
            int k = kb + ((c + 1) << 5) + lcol;
            pa0 = *reinterpret_cast<const float4*>(A + (long)lrow * lda + k);
            pa1 = *reinterpret_cast<const float4*>(A + (long)(lrow + 32) * lda + k);
            pw  = *reinterpret_cast<const float4*>(W + (long)(n0 + lrow) * CH + k);
        }
#pragma unroll
        for (int kk = 0; kk < 16; kk++) {
            u64 a2[4], w2[2];
#pragma unroll
            for (int i = 0; i < 4; i++)
                a2[i] = *reinterpret_cast<const u64*>(&As[tm + 16 * i][kk << 1]);
#pragma unroll
            for (int j = 0; j < 2; j++)
                w2[j] = *reinterpret_cast<const u64*>(&Ws[tn + 16 * j][kk << 1]);
#pragma unroll
            for (int i = 0; i < 4; i++)
#pragma unroll
                for (int j = 0; j < 2; j++) fma2(acc[i][j], a2[i], w2[j]);
        }
        __syncthreads();
    }
    float* out = part + (long)(bx >> 6) * 64 * G4;
#pragma unroll
    for (int i = 0; i < 4; i++)
#pragma unroll
        for (int j = 0; j < 2; j++)
            out[(tm + 16 * i) * G4 + n0 + tn + 16 * j] = pairsum(acc[i][j]);
}

__device__ __forceinline__ void gates_fn(const float* P, const float* D1, int ldd1,
                                         const float* D2, float* c,
                                         float* h_out, int h_ld, int idx)
{
    int b = idx >> 9, u = idx & 511;
    const float* g0 = P + (long)b * G4;
    const float* g1 = P + (long)CB * G4 + (long)b * G4;
    const float* d1 = D1 + (long)b * ldd1;
    float gi = g0[u]        + g1[u]        + d1[u];
    float gf = g0[512 + u]  + g1[512 + u]  + d1[512 + u];
    float gg = g0[1024 + u] + g1[1024 + u] + d1[1024 + u];
    float go = g0[1536 + u] + g1[1536 + u] + d1[1536 + u];
    if (D2) {
        const float* d2 = D2 + (long)b * G4;
        gi += d2[u]; gf += d2[512 + u]; gg += d2[1024 + u]; go += d2[1536 + u];
    }
    float i_ = 1.f / (1.f + expf(-gi));
    float f_ = 1.f / (1.f + expf(-gf));
    float g_ = tanhf(gg);
    float o_ = 1.f / (1.f + expf(-go));
    float cn = f_ * c[idx] + i_ * g_;
    c[idx] = cn;
    h_out[(long)b * h_ld + u] = o_ * tanhf(cn);
}

__global__ __launch_bounds__(256) void lstm_persist(
    const float* __restrict__ Whh,
    const float* __restrict__ gin, long gin_step, int gin_ld,
    const float* __restrict__ D2,
    const float* __restrict__ hz,
    float* __restrict__ hbase, long h_step, int h_ld,
    float* __restrict__ c, float* __restrict__ part,
    int nsteps, int dir)
{
    unsigned target = 0;
    const int bx = blockIdx.x;
    const int idx = bx * 256 + threadIdx.x;
    for (int s = 0; s < nsteps; s++) {
        int l = (dir > 0) ? s : (nsteps - 1 - s);
        const float* hin; int hlda;
        if (s == 0) { hin = hz; hlda = CH; }
        else {
            int lp = (dir > 0) ? (l - 1) : (l + 1);
            hin = hbase + (long)lp * h_step; hlda = h_ld;
        }
        step_gemm(hin, hlda, Whh, part, bx);
        grid_bar(target);
        gates_fn(part, gin + (long)l * gin_step, gin_ld, D2, c,
                 hbase + (long)l * h_step, h_ld, idx);
        if (s + 1 < nsteps) grid_bar(target);
        else                grid_bar_final(target);
    }
}

// ---------------- small elementwise kernels ----------------
__global__ void zero_state(float* cF, float* cB, float* cD, float* hz)
{
    int idx = blockIdx.x * blockDim.x + threadIdx.x;
    cF[idx] = 0.f; cB[idx] = 0.f; cD[idx] = 0.f; hz[idx] = 0.f;
}

__global__ void ctx_sum(const float* __restrict__ hF, const float* __restrict__ hB,
                        float* __restrict__ ctx)
{
    int idx = blockIdx.x * blockDim.x + threadIdx.x;  // 64*1024
    int b = idx >> 10, j = idx & 1023;
    float s = 0.f;
    if (j < 512) {
        for (int l = 0; l < CL; l++) s += hF[((long)l * CB + b) * CH + j];
    } else {
        int j2 = j - 512;
        for (int l = 0; l < CL; l++) s += hB[((long)l * CB + b) * CH + j2];
    }
    ctx[idx] = s;
}

__global__ void ctx_combine(const float* __restrict__ P,
                            const float* __restrict__ b0,
                            const float* __restrict__ b1,
                            float* __restrict__ ctxW)
{
    int idx = blockIdx.x * blockDim.x + threadIdx.x;  // 64*2048
    int b = idx >> 11, n = idx & 2047;
    float s = b0[n] + b1[n];
#pragma unroll
    for (int z = 0; z < 4; z++) s += P[((long)z * CB + b) * G4 + n];
    ctxW[idx] = s;
}

__global__ void gather_emb(const float* __restrict__ emb, const int* __restrict__ targets,
                           float* __restrict__ dst)
{
    int idx = blockIdx.x * blockDim.x + threadIdx.x;  // 39*64*512
    int e = idx & 511;
    int r = idx >> 9;
    int t = r / CB, b = r - t * CB;
    int tgt = targets[b * CL + t];
    dst[idx] = emb[(long)tgt * CE + e];
}

// ---------------- launch ----------------
static inline int sgrid(long n) { return (int)((n + 255) / 256); }

extern "C" void kernel_launch(void* const* d_in, const int* in_sizes, int n_in,
                              void* d_out, int out_size)
{
    (void)in_sizes; (void)n_in; (void)out_size;
    const float* feats  = (const float*)d_in[0];
    const float* feat_W = (const float*)d_in[1];
    const float* feat_b = (const float*)d_in[2];
    const float* Wih_f  = (const float*)d_in[3];
    const float* Whh_f  = (const float*)d_in[4];
    const float* bih_f  = (const float*)d_in[5];
    const float* bhh_f  = (const float*)d_in[6];
    const float* Wih_b  = (const float*)d_in[7];
    const float* Whh_b  = (const float*)d_in[8];
    const float* bih_b  = (const float*)d_in[9];
    const float* bhh_b  = (const float*)d_in[10];
    const float* emb    = (const float*)d_in[11];
    const float* Wih_d  = (const float*)d_in[12];
    const float* Whh_d  = (const float*)d_in[13];
    const float* bih_d  = (const float*)d_in[14];
    const float* bhh_d  = (const float*)d_in[15];
    // d_in[16..20]: attention params — provably unused (softmax over singleton axis -> ones)
    const float* out_W  = (const float*)d_in[21];
    const float* out_b  = (const float*)d_in[22];
    const int*   targets = (const int*)d_in[23];
    float* out = (float*)d_out;

    float* S = nullptr;
    cudaGetSymbolAddress((void**)&S, g_scratch);
    __nv_bfloat16* BF = nullptr;
    cudaGetSymbolAddress((void**)&BF, g_bf);

    float* x     = S + OFF_X;
    float* ginF  = S + OFF_GINF;
    float* ginB  = S + OFF_GINB;
    float* hF    = S + OFF_HF;
    float* hB    = S + OFF_HB;
    float* hD    = S + OFF_HD;
    float* cF    = S + OFF_CF;
    float* cBb   = S + OFF_CB2;
    float* cD    = S + OFF_CD;
    float* hz    = S + OFF_HZ;
    float* ctx   = S + OFF_CTX;
    float* demb  = S + OFF_DEMB;
    float* embW  = S + OFF_EMBW;
    float* ctxW  = S + OFF_CTXW;
    float* part  = S + OFF_PART;

    cudaFuncSetAttribute(gemm_mma, cudaFuncAttributeMaxDynamicSharedMemorySize, MMA_SMEM);

    zero_state<<<128, 256>>>(cF, cBb, cD, hz);

    // ---- weight/input splits to bf16 hi/lo ----
    split_bf16<<<sgrid(20096L*512), 256>>>(out_W, 512, 20000, 512,
                                           BF + BO_WOUT, 20096L*512, 20096L*512);
    split_bf16<<<sgrid(512L*2048), 256>>>(feat_W, 2048, 512, 2048,
                                          BF + BO_FW, 512L*2048, 512L*2048);
    split_bf16<<<sgrid(2048L*512), 256>>>(Wih_f, 512, 2048, 512,
                                          BF + BO_WIF, 2048L*512, 2048L*512);
    split_bf16<<<sgrid(2048L*512), 256>>>(Wih_b, 512, 2048, 512,
                                          BF + BO_WIB, 2048L*512, 2048L*512);
    split_bf16<<<sgrid(2048L*512), 256>>>(Wih_d, 2*CH + CE, 2048, 512,
                                          BF + BO_WID, 2048L*512, 2048L*512);
    split_bf16<<<sgrid(2560L*2048), 256>>>(feats, 2048, 2560, 2048,
                                           BF + BO_FEATS, 2560L*2048, 2560L*2048);

    // x = feats @ feat_W^T + feat_b     (HMMA, bf16x3 split, double-buffered)
    gemm_mma<<<dim3(20, 4), 256, MMA_SMEM>>>(BF + BO_FEATS, 2560L*2048, BF + BO_FW, 512L*2048,
                                             x, CH, 2560, CH, CDF, feat_b, nullptr);
    split_bf16<<<sgrid(2560L*512), 256>>>(x, 512, 2560, 512, BF + BO_X, 2560L*512, 2560L*512);

    // encoder input-gate precompute
    gemm_mma<<<dim3(20, 16), 256, MMA_SMEM>>>(BF + BO_X, 2560L*512, BF + BO_WIF, 2048L*512,
                                              ginF, G4, 2560, G4, CH, bih_f, bhh_f);
    gemm_mma<<<dim3(20, 16), 256, MMA_SMEM>>>(BF + BO_X, 2560L*512, BF + BO_WIB, 2048L*512,
                                              ginB, G4, 2560, G4, CH, bih_b, bhh_b);

    // forward + backward LSTMs (persistent)
    lstm_persist<<<128, 256>>>(Whh_f, ginF, (long)G4, CL * G4, nullptr, hz,
                               hF, (long)CB * CH, CH, cF, part, CL, +1);
    lstm_persist<<<128, 256>>>(Whh_b, ginB, (long)G4, CL * G4, nullptr, hz,
                               hB, (long)CB * CH, CH, cBb, part, CL, -1);

    // ctx[b] = sum_l enc[b,l,:]  (attention collapses: softmax over singleton axis)
    ctx_sum<<<256, 256>>>(hF, hB, ctx);

    // decoder input-gate precompute
    gather_emb<<<(CT * CB * CE) / 256, 256>>>(emb, targets, demb);
    split_bf16<<<sgrid(2560L*512), 256>>>(demb, 512, 2496, 512,
                                          BF + BO_DEMB, 2560L*512, 2560L*512);
    gemm_mma<<<dim3(20, 16), 256, MMA_SMEM>>>(BF + BO_DEMB, 2560L*512, BF + BO_WID, 2048L*512,
                                              embW, G4, 2496, G4, CE, nullptr, nullptr);
    gemm_small64<<<dim3(64, 4), 256>>>(ctx, 2 * CH, Wih_d + CE, 2 * CH + CE, part, G4, 256);
    ctx_combine<<<512, 256>>>(part, bih_d, bhh_d, ctxW);

    // decoder LSTM persistent (hD layout [B][T][H])
    lstm_persist<<<128, 256>>>(Whh_d, embW, (long)CB * G4, G4, ctxW, hz,
                               hD, (long)CH, CT * CH, cD, part, CT, +1);

    // output projection: out[b,t,:] = hD[b,t,:] @ out_W^T + out_b  (HMMA)
    split_bf16<<<sgrid(2560L*512), 256>>>(hD, 512, 2496, 512, BF + BO_HD, 2560L*512, 2560L*512);
    gemm_mma<<<dim3(20, 157), 256, MMA_SMEM>>>(BF + BO_HD, 2560L*512, BF + BO_WOUT, 20096L*512,
                                               out, CV, 2496, CV, CH, out_b, nullptr);
}